// round 11
// baseline (speedup 1.0000x reference)
#include <cuda_runtime.h>
#include <cuda_fp16.h>
#include <cstdint>

#define Bsz  4
#define Nseq 2048
#define Cdim 768
#define Hn   12
#define Dh   64
#define Mrows (Bsz * Nseq)   // 8192
#define SCALE_F 0.125f
#define LOG2E_F 1.4426950408889634f

// Scratch
__device__ __half g_wq[Cdim * Cdim];
__device__ __half g_wk[Cdim * Cdim];
__device__ __half g_wv[Cdim * Cdim];
__device__ __half g_wp[Cdim * Cdim];
__device__ __half g_q[Mrows * Cdim];   // [B,H,N,D], uc*SCALE*log2e folded
__device__ __half g_k[Mrows * Cdim];   // [B,H,N,D]
__device__ __half g_v[Mrows * Cdim];   // [B,H,N,D]
__device__ __half g_o[Mrows * Cdim];   // [B,N,C]
__device__ float  g_uc[Mrows];

// ---------------------------------------------------------------------------
__device__ __forceinline__ float ex2f(float x) {
    float y;
    asm("ex2.approx.f32 %0, %1;" : "=f"(y) : "f"(x));
    return y;
}
__device__ __forceinline__ uint32_t ex2h2(uint32_t x) {
    uint32_t y;
    asm("ex2.approx.f16x2 %0, %1;" : "=r"(y) : "r"(x));
    return y;
}
__device__ __forceinline__ uint32_t smem_u32(const void* p) {
    uint32_t a;
    asm("{ .reg .u64 t; cvta.to.shared.u64 t, %1; cvt.u32.u64 %0, t; }" : "=r"(a) : "l"(p));
    return a;
}
__device__ __forceinline__ uint32_t packh2(float a, float b) {
    __half2 h = __floats2half2_rn(a, b);
    return *(uint32_t*)&h;
}
#define CP16(dst, src) \
    asm volatile("cp.async.cg.shared.global [%0], [%1], 16;" :: "r"(dst), "l"(src))
#define CP_COMMIT() asm volatile("cp.async.commit_group;" ::: "memory")
#define CP_WAIT(n)  asm volatile("cp.async.wait_group %0;" :: "n"(n) : "memory")

#define LDSM4(r0, r1, r2, r3, addr) \
    asm volatile("ldmatrix.sync.aligned.m8n8.x4.shared.b16 {%0,%1,%2,%3}, [%4];" \
        : "=r"(r0), "=r"(r1), "=r"(r2), "=r"(r3) : "r"(addr))
#define LDSM4T(r0, r1, r2, r3, addr) \
    asm volatile("ldmatrix.sync.aligned.m8n8.x4.trans.shared.b16 {%0,%1,%2,%3}, [%4];" \
        : "=r"(r0), "=r"(r1), "=r"(r2), "=r"(r3) : "r"(addr))

__device__ __forceinline__ void mma16(float* d,
    uint32_t a0, uint32_t a1, uint32_t a2, uint32_t a3,
    uint32_t b0, uint32_t b1)
{
    asm("mma.sync.aligned.m16n8k16.row.col.f32.f16.f16.f32 "
        "{%0,%1,%2,%3},{%4,%5,%6,%7},{%8,%9},{%0,%1,%2,%3};"
        : "+f"(d[0]), "+f"(d[1]), "+f"(d[2]), "+f"(d[3])
        : "r"(a0), "r"(a1), "r"(a2), "r"(a3), "r"(b0), "r"(b1));
}

// ---------------------------------------------------------------------------
// One fused fp32->fp16 pass for the 4 weight matrices
// ---------------------------------------------------------------------------
__global__ void f2h4(const float* __restrict__ w0, const float* __restrict__ w1,
                     const float* __restrict__ w2, const float* __restrict__ w3,
                     __half* __restrict__ y0, __half* __restrict__ y1,
                     __half* __restrict__ y2, __half* __restrict__ y3)
{
    int which = blockIdx.y;
    const float* x = which == 0 ? w0 : which == 1 ? w1 : which == 2 ? w2 : w3;
    __half* y = which == 0 ? y0 : which == 1 ? y1 : which == 2 ? y2 : y3;
    int i = (blockIdx.x * blockDim.x + threadIdx.x) * 8;
    if (i >= Cdim * Cdim) return;
    float4 v0 = *(const float4*)(x + i);
    float4 v1 = *(const float4*)(x + i + 4);
    *(uint4*)(y + i) = make_uint4(packh2(v0.x, v0.y), packh2(v0.z, v0.w),
                                  packh2(v1.x, v1.y), packh2(v1.z, v1.w));
}

// ---------------------------------------------------------------------------
__global__ void uc_kernel(const float* __restrict__ xu, float* __restrict__ uc)
{
    int warp = (blockIdx.x * blockDim.x + threadIdx.x) >> 5;
    int lane = threadIdx.x & 31;
    if (warp >= Mrows) return;
    const float* row = xu + (size_t)warp * Cdim;
    float s = 0.0f;
#pragma unroll
    for (int i = 0; i < Cdim / 32; i++) s += row[lane + i * 32];
#pragma unroll
    for (int m = 16; m; m >>= 1) s += __shfl_xor_sync(0xffffffffu, s, m);
    if (lane == 0) uc[warp] = s * (1.0f / Cdim);
}

// ---------------------------------------------------------------------------
// Fused QKV projection GEMM, z-batched (unchanged, passing)
// ---------------------------------------------------------------------------
#define GQ_STRIDE  40
#define GQ_A_BYTES (128 * GQ_STRIDE * 2)   // 10240
#define GQ_SMEM    (3 * GQ_A_BYTES)        // 30720

__global__ __launch_bounds__(256, 2) void gemm_qkv(
    const float* __restrict__ xq, const float* __restrict__ xk,
    const float* __restrict__ xv,
    const __half* __restrict__ wq, const __half* __restrict__ wk,
    const __half* __restrict__ wv,
    const float* __restrict__ uc,
    __half* __restrict__ yq, __half* __restrict__ yk, __half* __restrict__ yv)
{
    extern __shared__ __half hs[];
    int z = blockIdx.z;
    const float*  A = z == 0 ? xq : z == 1 ? xk : xv;
    const __half* W = z == 0 ? wq : z == 1 ? wk : wv;
    __half*       Y = z == 0 ? yq : z == 1 ? yk : yv;

    int t = threadIdx.x, wid = t >> 5, lane = t & 31;
    int r = lane >> 2, c = lane & 3;
    int gi = lane & 7, gk = (lane >> 3) & 1, gh = lane >> 4;
    int wm = (wid >> 2) * 64, wn = (wid & 3) * 32;
    int m0 = blockIdx.y * 128, n0 = blockIdx.x * 128;
    uint32_t sA  = smem_u32(hs);
    uint32_t sW0 = sA + GQ_A_BYTES;

    float acc[4][4][4];
#pragma unroll
    for (int mt = 0; mt < 4; mt++)
#pragma unroll
        for (int nt = 0; nt < 4; nt++)
#pragma unroll
            for (int i = 0; i < 4; i++) acc[mt][nt][i] = 0.0f;

    int arow = t >> 1, acg = (t & 1) * 16;
    const float* Ap = A + (size_t)(m0 + arow) * Cdim + acg;
    float4 a4[4];

#define QKV_LOADA(kt) do { int _kb = (kt) * 32;                                  \
    a4[0] = *(const float4*)(Ap + _kb);      a4[1] = *(const float4*)(Ap + _kb + 4);  \
    a4[2] = *(const float4*)(Ap + _kb + 8);  a4[3] = *(const float4*)(Ap + _kb + 12); \
} while (0)

#define QKV_STSA() do {                                                          \
    uint4 u0 = make_uint4(packh2(a4[0].x, a4[0].y), packh2(a4[0].z, a4[0].w),    \
                          packh2(a4[1].x, a4[1].y), packh2(a4[1].z, a4[1].w));   \
    uint4 u1 = make_uint4(packh2(a4[2].x, a4[2].y), packh2(a4[2].z, a4[2].w),    \
                          packh2(a4[3].x, a4[3].y), packh2(a4[3].z, a4[3].w));   \
    *(uint4*)((char*)hs + (arow * GQ_STRIDE + acg) * 2) = u0;                    \
    *(uint4*)((char*)hs + (arow * GQ_STRIDE + acg + 8) * 2) = u1;                \
} while (0)

#define QKV_CPW(kt) do { int _kb = (kt) * 32;                                    \
    uint32_t _bw = sW0 + ((kt) & 1) * GQ_A_BYTES;                                \
    _Pragma("unroll")                                                            \
    for (int j = 0; j < 2; j++) {                                                \
        int idx = t * 2 + j;                                                     \
        int row = idx >> 2, ch = idx & 3;                                        \
        CP16(_bw + (row * GQ_STRIDE + ch * 8) * 2,                               \
             W + (size_t)(n0 + row) * Cdim + _kb + ch * 8);                      \
    }                                                                            \
} while (0)

    QKV_LOADA(0);
    QKV_CPW(0); CP_COMMIT();
    QKV_STSA();
    __syncthreads();

    const int NT = Cdim / 32;   // 24
    for (int kt = 0; kt < NT; kt++) {
        if (kt + 1 < NT) { QKV_LOADA(kt + 1); QKV_CPW(kt + 1); CP_COMMIT(); }
        if (kt < NT - 1) { CP_WAIT(1); } else { CP_WAIT(0); }
        __syncthreads();

        uint32_t bW = sW0 + (kt & 1) * GQ_A_BYTES;
#pragma unroll
        for (int kk = 0; kk < 32; kk += 16) {
            uint32_t a[4][4], bb[2][4];
#pragma unroll
            for (int mt = 0; mt < 4; mt++)
                LDSM4(a[mt][0], a[mt][1], a[mt][2], a[mt][3],
                      sA + ((wm + mt * 16 + gi + gk * 8) * GQ_STRIDE + kk + gh * 8) * 2);
#pragma unroll
            for (int bt = 0; bt < 2; bt++)
                LDSM4(bb[bt][0], bb[bt][1], bb[bt][2], bb[bt][3],
                      bW + ((wn + bt * 16 + gi + gk * 8) * GQ_STRIDE + kk + gh * 8) * 2);
#pragma unroll
            for (int mt = 0; mt < 4; mt++)
#pragma unroll
                for (int nt = 0; nt < 4; nt++) {
                    int bt = nt >> 1, od = nt & 1;
                    mma16(acc[mt][nt], a[mt][0], a[mt][1], a[mt][2], a[mt][3],
                          bb[bt][od ? 1 : 0], bb[bt][od ? 3 : 2]);
                }
        }
        __syncthreads();
        if (kt + 1 < NT) QKV_STSA();
    }

#pragma unroll
    for (int mt = 0; mt < 4; mt++) {
        int mA = m0 + wm + mt * 16 + r;
        int mB = mA + 8;
        float sAs = 1.0f, sBs = 1.0f;
        if (z == 0) {
            sAs = uc[mA] * (SCALE_F * LOG2E_F);
            sBs = uc[mB] * (SCALE_F * LOG2E_F);
        }
        int bA = mA >> 11, nA = mA & (Nseq - 1);
        int bB = mB >> 11, nB = mB & (Nseq - 1);
#pragma unroll
        for (int nt = 0; nt < 4; nt++) {
            int n = n0 + wn + nt * 8 + 2 * c;
            int h = n >> 6, d = n & 63;
            *(uint32_t*)&Y[(((size_t)(bA * Hn + h) * Nseq + nA) << 6) + d] =
                packh2(acc[mt][nt][0] * sAs, acc[mt][nt][1] * sAs);
            *(uint32_t*)&Y[(((size_t)(bB * Hn + h) * Nseq + nB) << 6) + d] =
                packh2(acc[mt][nt][2] * sBs, acc[mt][nt][3] * sBs);
        }
    }
}

// ---------------------------------------------------------------------------
// Output GEMM: out = O[M,C] @ Wp^T + bp.  128x64 tiles (tail packing),
// BK=64, occupancy 3.  Grid (12, 64) = 768 CTAs.
// ---------------------------------------------------------------------------
#define GO_STRIDE 72
#define GO_A_B    (128 * GO_STRIDE * 2)        // 18432
#define GO_W_B    (64 * GO_STRIDE * 2)         // 9216
#define GO_STG    (GO_A_B + GO_W_B)            // 27648
#define GO_SMEM   (2 * GO_STG)                 // 55296

__global__ __launch_bounds__(256, 3) void gemm_out(
    const __half* __restrict__ A, const __half* __restrict__ W,
    const float* __restrict__ bias, float* __restrict__ Y)
{
    extern __shared__ __half hs[];
    int t = threadIdx.x, wid = t >> 5, lane = t & 31;
    int r = lane >> 2, c = lane & 3;
    int gi = lane & 7, gk = (lane >> 3) & 1, gh = lane >> 4;
    int wm = (wid >> 2) * 64, wn = (wid & 3) * 16;
    int m0 = blockIdx.y * 128, n0 = blockIdx.x * 64;
    uint32_t sbase = smem_u32(hs);

    float acc[4][2][4];
#pragma unroll
    for (int mt = 0; mt < 4; mt++)
#pragma unroll
        for (int nt = 0; nt < 2; nt++)
#pragma unroll
            for (int i = 0; i < 4; i++) acc[mt][nt][i] = 0.0f;

#define GO_PREFETCH(kt) do {                                                     \
    uint32_t _dA = sbase + ((kt) & 1) * GO_STG;                                  \
    uint32_t _dW = _dA + GO_A_B;                                                 \
    int _kb = (kt) * 64;                                                         \
    _Pragma("unroll")                                                            \
    for (int j = 0; j < 4; j++) {                                                \
        int idx = t * 4 + j;                                                     \
        int row = idx >> 3, ch = idx & 7;                                        \
        CP16(_dA + (row * GO_STRIDE + ch * 8) * 2,                               \
             A + (size_t)(m0 + row) * Cdim + _kb + ch * 8);                      \
    }                                                                            \
    _Pragma("unroll")                                                            \
    for (int j = 0; j < 2; j++) {                                                \
        int idx = t * 2 + j;                                                     \
        int row = idx >> 3, ch = idx & 7;                                        \
        CP16(_dW + (row * GO_STRIDE + ch * 8) * 2,                               \
             W + (size_t)(n0 + row) * Cdim + _kb + ch * 8);                      \
    }                                                                            \
} while (0)

    GO_PREFETCH(0);
    CP_COMMIT();

    const int NT = Cdim / 64;   // 12
    for (int kt = 0; kt < NT; kt++) {
        if (kt + 1 < NT) { GO_PREFETCH(kt + 1); CP_COMMIT(); CP_WAIT(1); }
        else             { CP_WAIT(0); }
        __syncthreads();

        uint32_t sA = sbase + (kt & 1) * GO_STG;
        uint32_t sW = sA + GO_A_B;
#pragma unroll
        for (int kk = 0; kk < 64; kk += 16) {
            uint32_t a[4][4], bb[4];
#pragma unroll
            for (int mt = 0; mt < 4; mt++)
                LDSM4(a[mt][0], a[mt][1], a[mt][2], a[mt][3],
                      sA + ((wm + mt * 16 + gi + gk * 8) * GO_STRIDE + kk + gh * 8) * 2);
            LDSM4(bb[0], bb[1], bb[2], bb[3],
                  sW + ((wn + gi + gk * 8) * GO_STRIDE + kk + gh * 8) * 2);
#pragma unroll
            for (int mt = 0; mt < 4; mt++) {
                mma16(acc[mt][0], a[mt][0], a[mt][1], a[mt][2], a[mt][3], bb[0], bb[2]);
                mma16(acc[mt][1], a[mt][0], a[mt][1], a[mt][2], a[mt][3], bb[1], bb[3]);
            }
        }
        __syncthreads();
    }

#pragma unroll
    for (int mt = 0; mt < 4; mt++) {
        int mA = m0 + wm + mt * 16 + r;
        int mB = mA + 8;
#pragma unroll
        for (int nt = 0; nt < 2; nt++) {
            int n = n0 + wn + nt * 8 + 2 * c;
            float2 bv = *(const float2*)&bias[n];
            *(float2*)&Y[(size_t)mA * Cdim + n] =
                make_float2(acc[mt][nt][0] + bv.x, acc[mt][nt][1] + bv.y);
            *(float2*)&Y[(size_t)mB * Cdim + n] =
                make_float2(acc[mt][nt][2] + bv.x, acc[mt][nt][3] + bv.y);
        }
    }
}

// ---------------------------------------------------------------------------
// fp16 flash attention: 128 q/CTA; 128-key superblocks double-buffered.
// Q fragments hoisted to registers (loop-invariant). fp16x2 exp softmax,
// row sums via mma-with-ones.
// ---------------------------------------------------------------------------
#define AT_STRIDE 72
#define AT_QB     (128 * AT_STRIDE * 2)    // 18432 bytes (Q)
#define AT_CH     (64 * AT_STRIDE * 2)     // 9216 bytes per 64-key chunk
#define AT_SMEM   (AT_QB + 8 * AT_CH)      // 92160
#define ONES_H2   0x3C003C00u

__global__ __launch_bounds__(256, 2) void attn_h(
    const __half* __restrict__ Q, const __half* __restrict__ K,
    const __half* __restrict__ V, __half* __restrict__ O)
{
    extern __shared__ __half hs[];
    uint32_t sQ  = smem_u32(hs);
    uint32_t sKb = sQ + AT_QB;
    uint32_t sVb = sKb + 4 * AT_CH;

    int t = threadIdx.x, wid = t >> 5, lane = t & 31;
    int r = lane >> 2, c = lane & 3;
    int gi = lane & 7, gk = (lane >> 3) & 1, gh = lane >> 4;
    int bh = blockIdx.y;
    int b = bh / Hn, h = bh - b * Hn;
    int q0 = blockIdx.x * 128;
    int wm = wid * 16;

    const __half* Qb = Q + ((size_t)bh * Nseq + q0) * Dh;
    const __half* Kb = K + (size_t)bh * Nseq * Dh;
    const __half* Vb = V + (size_t)bh * Nseq * Dh;

#pragma unroll
    for (int j = 0; j < 4; j++) {
        int idx = t * 4 + j;
        int row = idx >> 3, ch = idx & 7;
        CP16(sQ + (row * AT_STRIDE + ch * 8) * 2, Qb + (size_t)row * Dh + ch * 8);
    }

#define AT_PREFETCH(sb, kt0) do {                                                \
    _Pragma("unroll")                                                            \
    for (int j = 0; j < 4; j++) {                                                \
        int idx = t * 4 + j;                                                     \
        int row = idx >> 3, ch = idx & 7;                                        \
        int hh = row >> 6, rr = row & 63;                                        \
        CP16(sKb + ((sb) * 2 + hh) * AT_CH + (rr * AT_STRIDE + ch * 8) * 2,      \
             Kb + (size_t)((kt0) + row) * Dh + ch * 8);                          \
    }                                                                            \
    _Pragma("unroll")                                                            \
    for (int j = 0; j < 4; j++) {                                                \
        int idx = t * 4 + j;                                                     \
        int row = idx >> 3, ch = idx & 7;                                        \
        int hh = row >> 6, rr = row & 63;                                        \
        CP16(sVb + ((sb) * 2 + hh) * AT_CH + (rr * AT_STRIDE + ch * 8) * 2,      \
             Vb + (size_t)((kt0) + row) * Dh + ch * 8);                          \
    }                                                                            \
} while (0)

    AT_PREFETCH(0, 0);
    CP_COMMIT();

    // Q staged with superblock 0 — wait once, hoist Q fragments to registers.
    CP_WAIT(0);
    __syncthreads();
    uint32_t qf[4][4];
#pragma unroll
    for (int ks = 0; ks < 4; ks++)
        LDSM4(qf[ks][0], qf[ks][1], qf[ks][2], qf[ks][3],
              sQ + ((wm + gi + gk * 8) * AT_STRIDE + ks * 16 + gh * 8) * 2);

    float m_[2] = { -1e30f, -1e30f };
    float lsum[4] = { 0.0f, 0.0f, 0.0f, 0.0f };
    float o[8][4];
#pragma unroll
    for (int nt = 0; nt < 8; nt++)
#pragma unroll
        for (int i = 0; i < 4; i++) o[nt][i] = 0.0f;

    const int NSB = Nseq / 128;   // 16 superblocks
    for (int it = 0; it < NSB; it++) {
        CP_WAIT(0);
        __syncthreads();

        if (it + 1 < NSB) {
            AT_PREFETCH((it + 1) & 1, (it + 1) * 128);
            CP_COMMIT();
        }

        uint32_t kbase = sKb + (it & 1) * 2 * AT_CH;
        uint32_t vbase = sVb + (it & 1) * 2 * AT_CH;

#pragma unroll
        for (int hh = 0; hh < 2; hh++) {
            uint32_t sK = kbase + hh * AT_CH;
            uint32_t sV = vbase + hh * AT_CH;

            // ---- S = Q K^T (Q from registers) ----
            float s[8][4];
#pragma unroll
            for (int nt = 0; nt < 8; nt++)
#pragma unroll
                for (int i = 0; i < 4; i++) s[nt][i] = 0.0f;

#pragma unroll
            for (int ks = 0; ks < 4; ks++) {
                int d0 = ks * 16;
#pragma unroll
                for (int kn = 0; kn < 4; kn++) {
                    uint32_t b0, b1, b2, b3;
                    LDSM4(b0, b1, b2, b3,
                          sK + ((kn * 16 + gi + gk * 8) * AT_STRIDE + d0 + gh * 8) * 2);
                    mma16(s[kn * 2    ], qf[ks][0], qf[ks][1], qf[ks][2], qf[ks][3], b0, b2);
                    mma16(s[kn * 2 + 1], qf[ks][0], qf[ks][1], qf[ks][2], qf[ks][3], b1, b3);
                }
            }

            // ---- row max (fp32) ----
            float mx0 = -1e30f, mx1 = -1e30f;
#pragma unroll
            for (int nt = 0; nt < 8; nt++) {
                mx0 = fmaxf(mx0, fmaxf(s[nt][0], s[nt][1]));
                mx1 = fmaxf(mx1, fmaxf(s[nt][2], s[nt][3]));
            }
            mx0 = fmaxf(mx0, __shfl_xor_sync(0xffffffffu, mx0, 1));
            mx0 = fmaxf(mx0, __shfl_xor_sync(0xffffffffu, mx0, 2));
            mx1 = fmaxf(mx1, __shfl_xor_sync(0xffffffffu, mx1, 1));
            mx1 = fmaxf(mx1, __shfl_xor_sync(0xffffffffu, mx1, 2));

            float mn0 = fmaxf(m_[0], mx0);
            float mn1 = fmaxf(m_[1], mx1);
            float cor0 = ex2f(m_[0] - mn0);
            float cor1 = ex2f(m_[1] - mn1);
            m_[0] = mn0; m_[1] = mn1;

            // ---- P = exp2(S - m) in fp16x2 ----
            uint32_t pp[8][2];
#pragma unroll
            for (int nt = 0; nt < 8; nt++) {
                pp[nt][0] = ex2h2(packh2(s[nt][0] - mn0, s[nt][1] - mn0));
                pp[nt][1] = ex2h2(packh2(s[nt][2] - mn1, s[nt][3] - mn1));
            }

            // ---- rescale O and lsum ----
#pragma unroll
            for (int nt = 0; nt < 8; nt++) {
                o[nt][0] *= cor0; o[nt][1] *= cor0;
                o[nt][2] *= cor1; o[nt][3] *= cor1;
            }
            lsum[0] *= cor0; lsum[1] *= cor0;
            lsum[2] *= cor1; lsum[3] *= cor1;

            // ---- lsum += P @ ones ; O += P V ----
#pragma unroll
            for (int ks = 0; ks < 4; ks++) {
                uint32_t pa0 = pp[2 * ks][0];
                uint32_t pa1 = pp[2 * ks][1];
                uint32_t pa2 = pp[2 * ks + 1][0];
                uint32_t pa3 = pp[2 * ks + 1][1];
                mma16(lsum, pa0, pa1, pa2, pa3, ONES_H2, ONES_H2);
#pragma unroll
                for (int dn = 0; dn < 4; dn++) {
                    uint32_t b0, b1, b2, b3;
                    LDSM4T(b0, b1, b2, b3,
                           sV + ((ks * 16 + gi + gk * 8) * AT_STRIDE + dn * 16 + gh * 8) * 2);
                    mma16(o[dn * 2    ], pa0, pa1, pa2, pa3, b0, b1);
                    mma16(o[dn * 2 + 1], pa0, pa1, pa2, pa3, b2, b3);
                }
            }
        }
    }

    float inv0 = 1.0f / lsum[0];
    float inv1 = 1.0f / lsum[2];
    int qg0 = q0 + wm + r;
    int qg1 = qg0 + 8;
#pragma unroll
    for (int nt = 0; nt < 8; nt++) {
        int d = h * Dh + nt * 8 + 2 * c;
        *(uint32_t*)&O[(size_t)(b * Nseq + qg0) * Cdim + d] =
            packh2(o[nt][0] * inv0, o[nt][1] * inv0);
        *(uint32_t*)&O[(size_t)(b * Nseq + qg1) * Cdim + d] =
            packh2(o[nt][2] * inv1, o[nt][3] * inv1);
    }
}

// ---------------------------------------------------------------------------
extern "C" void kernel_launch(void* const* d_in, const int* in_sizes, int n_in,
                              void* d_out, int out_size)
{
    const float* x_q = (const float*)d_in[0];
    const float* x_k = (const float*)d_in[1];
    const float* x_v = (const float*)d_in[2];
    const float* x_u = (const float*)d_in[3];
    const float* Wq  = (const float*)d_in[4];
    const float* Wk  = (const float*)d_in[5];
    const float* Wv  = (const float*)d_in[6];
    const float* Wp  = (const float*)d_in[7];
    const float* bp  = (const float*)d_in[8];
    float* out = (float*)d_out;

    __half *hwq, *hwk, *hwv, *hwp, *hq, *hk, *hv, *ho;
    float *guc;
    cudaGetSymbolAddress((void**)&hwq, g_wq);
    cudaGetSymbolAddress((void**)&hwk, g_wk);
    cudaGetSymbolAddress((void**)&hwv, g_wv);
    cudaGetSymbolAddress((void**)&hwp, g_wp);
    cudaGetSymbolAddress((void**)&hq,  g_q);
    cudaGetSymbolAddress((void**)&hk,  g_k);
    cudaGetSymbolAddress((void**)&hv,  g_v);
    cudaGetSymbolAddress((void**)&ho,  g_o);
    cudaGetSymbolAddress((void**)&guc, g_uc);

    cudaFuncSetAttribute(attn_h,   cudaFuncAttributeMaxDynamicSharedMemorySize, AT_SMEM);
    cudaFuncSetAttribute(gemm_qkv, cudaFuncAttributeMaxDynamicSharedMemorySize, GQ_SMEM);
    cudaFuncSetAttribute(gemm_out, cudaFuncAttributeMaxDynamicSharedMemorySize, GO_SMEM);

    const int NW = Cdim * Cdim;   // 589824
    dim3 f2h_grid(NW / 2048, 4);
    f2h4<<<f2h_grid, 256>>>(Wq, Wk, Wv, Wp, hwq, hwk, hwv, hwp);

    uc_kernel<<<Mrows / 8, 256>>>(x_u, guc);

    dim3 qkv_grid(Cdim / 128, Mrows / 128, 3);   // (6, 64, 3)
    gemm_qkv<<<qkv_grid, 256, GQ_SMEM>>>(x_q, x_k, x_v, hwq, hwk, hwv,
                                         guc, hq, hk, hv);

    dim3 attn_grid(Nseq / 128, Bsz * Hn);        // (16, 48)
    attn_h<<<attn_grid, 256, AT_SMEM>>>(hq, hk, hv, ho);

    dim3 out_grid(Cdim / 64, Mrows / 128);       // (12, 64)
    gemm_out<<<out_grid, 256, GO_SMEM>>>(ho, hwp, bp, out);
}

// round 12
// speedup vs baseline: 1.0099x; 1.0099x over previous
#include <cuda_runtime.h>
#include <cuda_fp16.h>
#include <cstdint>

#define Bsz  4
#define Nseq 2048
#define Cdim 768
#define Hn   12
#define Dh   64
#define Mrows (Bsz * Nseq)   // 8192
#define SCALE_F 0.125f
#define LOG2E_F 1.4426950408889634f

// Scratch
__device__ __half g_wq[Cdim * Cdim];
__device__ __half g_wk[Cdim * Cdim];
__device__ __half g_wv[Cdim * Cdim];
__device__ __half g_wp[Cdim * Cdim];
__device__ __half g_q[Mrows * Cdim];   // [B,H,N,D], uc*SCALE*log2e folded
__device__ __half g_k[Mrows * Cdim];   // [B,H,N,D]
__device__ __half g_v[Mrows * Cdim];   // [B,H,N,D]
__device__ __half g_o[Mrows * Cdim];   // [B,N,C]
__device__ float  g_uc[Mrows];

// ---------------------------------------------------------------------------
__device__ __forceinline__ float ex2f(float x) {
    float y;
    asm("ex2.approx.f32 %0, %1;" : "=f"(y) : "f"(x));
    return y;
}
__device__ __forceinline__ uint32_t ex2h2(uint32_t x) {
    uint32_t y;
    asm("ex2.approx.f16x2 %0, %1;" : "=r"(y) : "r"(x));
    return y;
}
__device__ __forceinline__ uint32_t smem_u32(const void* p) {
    uint32_t a;
    asm("{ .reg .u64 t; cvta.to.shared.u64 t, %1; cvt.u32.u64 %0, t; }" : "=r"(a) : "l"(p));
    return a;
}
__device__ __forceinline__ uint32_t packh2(float a, float b) {
    __half2 h = __floats2half2_rn(a, b);
    return *(uint32_t*)&h;
}
#define CP16(dst, src) \
    asm volatile("cp.async.cg.shared.global [%0], [%1], 16;" :: "r"(dst), "l"(src))
#define CP_COMMIT() asm volatile("cp.async.commit_group;" ::: "memory")
#define CP_WAIT(n)  asm volatile("cp.async.wait_group %0;" :: "n"(n) : "memory")

#define LDSM4(r0, r1, r2, r3, addr) \
    asm volatile("ldmatrix.sync.aligned.m8n8.x4.shared.b16 {%0,%1,%2,%3}, [%4];" \
        : "=r"(r0), "=r"(r1), "=r"(r2), "=r"(r3) : "r"(addr))
#define LDSM4T(r0, r1, r2, r3, addr) \
    asm volatile("ldmatrix.sync.aligned.m8n8.x4.trans.shared.b16 {%0,%1,%2,%3}, [%4];" \
        : "=r"(r0), "=r"(r1), "=r"(r2), "=r"(r3) : "r"(addr))

__device__ __forceinline__ void mma16(float* d,
    uint32_t a0, uint32_t a1, uint32_t a2, uint32_t a3,
    uint32_t b0, uint32_t b1)
{
    asm("mma.sync.aligned.m16n8k16.row.col.f32.f16.f16.f32 "
        "{%0,%1,%2,%3},{%4,%5,%6,%7},{%8,%9},{%0,%1,%2,%3};"
        : "+f"(d[0]), "+f"(d[1]), "+f"(d[2]), "+f"(d[3])
        : "r"(a0), "r"(a1), "r"(a2), "r"(a3), "r"(b0), "r"(b1));
}

// ---------------------------------------------------------------------------
// One fused fp32->fp16 pass for the 4 weight matrices
// ---------------------------------------------------------------------------
__global__ void f2h4(const float* __restrict__ w0, const float* __restrict__ w1,
                     const float* __restrict__ w2, const float* __restrict__ w3,
                     __half* __restrict__ y0, __half* __restrict__ y1,
                     __half* __restrict__ y2, __half* __restrict__ y3)
{
    int which = blockIdx.y;
    const float* x = which == 0 ? w0 : which == 1 ? w1 : which == 2 ? w2 : w3;
    __half* y = which == 0 ? y0 : which == 1 ? y1 : which == 2 ? y2 : y3;
    int i = (blockIdx.x * blockDim.x + threadIdx.x) * 8;
    if (i >= Cdim * Cdim) return;
    float4 v0 = *(const float4*)(x + i);
    float4 v1 = *(const float4*)(x + i + 4);
    *(uint4*)(y + i) = make_uint4(packh2(v0.x, v0.y), packh2(v0.z, v0.w),
                                  packh2(v1.x, v1.y), packh2(v1.z, v1.w));
}

// ---------------------------------------------------------------------------
__global__ void uc_kernel(const float* __restrict__ xu, float* __restrict__ uc)
{
    int warp = (blockIdx.x * blockDim.x + threadIdx.x) >> 5;
    int lane = threadIdx.x & 31;
    if (warp >= Mrows) return;
    const float* row = xu + (size_t)warp * Cdim;
    float s = 0.0f;
#pragma unroll
    for (int i = 0; i < Cdim / 32; i++) s += row[lane + i * 32];
#pragma unroll
    for (int m = 16; m; m >>= 1) s += __shfl_xor_sync(0xffffffffu, s, m);
    if (lane == 0) uc[warp] = s * (1.0f / Cdim);
}

// ---------------------------------------------------------------------------
// Fused QKV projection GEMM, z-batched (unchanged, passing)
// ---------------------------------------------------------------------------
#define GQ_STRIDE  40
#define GQ_A_BYTES (128 * GQ_STRIDE * 2)   // 10240
#define GQ_SMEM    (3 * GQ_A_BYTES)        // 30720

__global__ __launch_bounds__(256, 2) void gemm_qkv(
    const float* __restrict__ xq, const float* __restrict__ xk,
    const float* __restrict__ xv,
    const __half* __restrict__ wq, const __half* __restrict__ wk,
    const __half* __restrict__ wv,
    const float* __restrict__ uc,
    __half* __restrict__ yq, __half* __restrict__ yk, __half* __restrict__ yv)
{
    extern __shared__ __half hs[];
    int z = blockIdx.z;
    const float*  A = z == 0 ? xq : z == 1 ? xk : xv;
    const __half* W = z == 0 ? wq : z == 1 ? wk : wv;
    __half*       Y = z == 0 ? yq : z == 1 ? yk : yv;

    int t = threadIdx.x, wid = t >> 5, lane = t & 31;
    int r = lane >> 2, c = lane & 3;
    int gi = lane & 7, gk = (lane >> 3) & 1, gh = lane >> 4;
    int wm = (wid >> 2) * 64, wn = (wid & 3) * 32;
    int m0 = blockIdx.y * 128, n0 = blockIdx.x * 128;
    uint32_t sA  = smem_u32(hs);
    uint32_t sW0 = sA + GQ_A_BYTES;

    float acc[4][4][4];
#pragma unroll
    for (int mt = 0; mt < 4; mt++)
#pragma unroll
        for (int nt = 0; nt < 4; nt++)
#pragma unroll
            for (int i = 0; i < 4; i++) acc[mt][nt][i] = 0.0f;

    int arow = t >> 1, acg = (t & 1) * 16;
    const float* Ap = A + (size_t)(m0 + arow) * Cdim + acg;
    float4 a4[4];

#define QKV_LOADA(kt) do { int _kb = (kt) * 32;                                  \
    a4[0] = *(const float4*)(Ap + _kb);      a4[1] = *(const float4*)(Ap + _kb + 4);  \
    a4[2] = *(const float4*)(Ap + _kb + 8);  a4[3] = *(const float4*)(Ap + _kb + 12); \
} while (0)

#define QKV_STSA() do {                                                          \
    uint4 u0 = make_uint4(packh2(a4[0].x, a4[0].y), packh2(a4[0].z, a4[0].w),    \
                          packh2(a4[1].x, a4[1].y), packh2(a4[1].z, a4[1].w));   \
    uint4 u1 = make_uint4(packh2(a4[2].x, a4[2].y), packh2(a4[2].z, a4[2].w),    \
                          packh2(a4[3].x, a4[3].y), packh2(a4[3].z, a4[3].w));   \
    *(uint4*)((char*)hs + (arow * GQ_STRIDE + acg) * 2) = u0;                    \
    *(uint4*)((char*)hs + (arow * GQ_STRIDE + acg + 8) * 2) = u1;                \
} while (0)

#define QKV_CPW(kt) do { int _kb = (kt) * 32;                                    \
    uint32_t _bw = sW0 + ((kt) & 1) * GQ_A_BYTES;                                \
    _Pragma("unroll")                                                            \
    for (int j = 0; j < 2; j++) {                                                \
        int idx = t * 2 + j;                                                     \
        int row = idx >> 2, ch = idx & 3;                                        \
        CP16(_bw + (row * GQ_STRIDE + ch * 8) * 2,                               \
             W + (size_t)(n0 + row) * Cdim + _kb + ch * 8);                      \
    }                                                                            \
} while (0)

    QKV_LOADA(0);
    QKV_CPW(0); CP_COMMIT();
    QKV_STSA();
    __syncthreads();

    const int NT = Cdim / 32;   // 24
    for (int kt = 0; kt < NT; kt++) {
        if (kt + 1 < NT) { QKV_LOADA(kt + 1); QKV_CPW(kt + 1); CP_COMMIT(); }
        if (kt < NT - 1) { CP_WAIT(1); } else { CP_WAIT(0); }
        __syncthreads();

        uint32_t bW = sW0 + (kt & 1) * GQ_A_BYTES;
#pragma unroll
        for (int kk = 0; kk < 32; kk += 16) {
            uint32_t a[4][4], bb[2][4];
#pragma unroll
            for (int mt = 0; mt < 4; mt++)
                LDSM4(a[mt][0], a[mt][1], a[mt][2], a[mt][3],
                      sA + ((wm + mt * 16 + gi + gk * 8) * GQ_STRIDE + kk + gh * 8) * 2);
#pragma unroll
            for (int bt = 0; bt < 2; bt++)
                LDSM4(bb[bt][0], bb[bt][1], bb[bt][2], bb[bt][3],
                      bW + ((wn + bt * 16 + gi + gk * 8) * GQ_STRIDE + kk + gh * 8) * 2);
#pragma unroll
            for (int mt = 0; mt < 4; mt++)
#pragma unroll
                for (int nt = 0; nt < 4; nt++) {
                    int bt = nt >> 1, od = nt & 1;
                    mma16(acc[mt][nt], a[mt][0], a[mt][1], a[mt][2], a[mt][3],
                          bb[bt][od ? 1 : 0], bb[bt][od ? 3 : 2]);
                }
        }
        __syncthreads();
        if (kt + 1 < NT) QKV_STSA();
    }

#pragma unroll
    for (int mt = 0; mt < 4; mt++) {
        int mA = m0 + wm + mt * 16 + r;
        int mB = mA + 8;
        float sAs = 1.0f, sBs = 1.0f;
        if (z == 0) {
            sAs = uc[mA] * (SCALE_F * LOG2E_F);
            sBs = uc[mB] * (SCALE_F * LOG2E_F);
        }
        int bA = mA >> 11, nA = mA & (Nseq - 1);
        int bB = mB >> 11, nB = mB & (Nseq - 1);
#pragma unroll
        for (int nt = 0; nt < 4; nt++) {
            int n = n0 + wn + nt * 8 + 2 * c;
            int h = n >> 6, d = n & 63;
            *(uint32_t*)&Y[(((size_t)(bA * Hn + h) * Nseq + nA) << 6) + d] =
                packh2(acc[mt][nt][0] * sAs, acc[mt][nt][1] * sAs);
            *(uint32_t*)&Y[(((size_t)(bB * Hn + h) * Nseq + nB) << 6) + d] =
                packh2(acc[mt][nt][2] * sBs, acc[mt][nt][3] * sBs);
        }
    }
}

// ---------------------------------------------------------------------------
// Output GEMM (REVERTED to round-10 config): 128x128, BK=64, occ 2.
// ---------------------------------------------------------------------------
#define GO_STRIDE 72
#define GO_MAT    (128 * GO_STRIDE * 2)    // 18432
#define GO_STG    (2 * GO_MAT)             // 36864
#define GO_SMEM   (2 * GO_STG)             // 73728

__global__ __launch_bounds__(256, 2) void gemm_out(
    const __half* __restrict__ A, const __half* __restrict__ W,
    const float* __restrict__ bias, float* __restrict__ Y)
{
    extern __shared__ __half hs[];
    int t = threadIdx.x, wid = t >> 5, lane = t & 31;
    int r = lane >> 2, c = lane & 3;
    int gi = lane & 7, gk = (lane >> 3) & 1, gh = lane >> 4;
    int wm = (wid >> 2) * 64, wn = (wid & 3) * 32;
    int m0 = blockIdx.y * 128, n0 = blockIdx.x * 128;
    uint32_t sbase = smem_u32(hs);

    float acc[4][4][4];
#pragma unroll
    for (int mt = 0; mt < 4; mt++)
#pragma unroll
        for (int nt = 0; nt < 4; nt++)
#pragma unroll
            for (int i = 0; i < 4; i++) acc[mt][nt][i] = 0.0f;

#define GO_PREFETCH(kt) do {                                                     \
    uint32_t _dA = sbase + ((kt) & 1) * GO_STG;                                  \
    uint32_t _dW = _dA + GO_MAT;                                                 \
    int _kb = (kt) * 64;                                                         \
    _Pragma("unroll")                                                            \
    for (int j = 0; j < 4; j++) {                                                \
        int idx = t * 4 + j;                                                     \
        int row = idx >> 3, ch = idx & 7;                                        \
        CP16(_dA + (row * GO_STRIDE + ch * 8) * 2,                               \
             A + (size_t)(m0 + row) * Cdim + _kb + ch * 8);                      \
        CP16(_dW + (row * GO_STRIDE + ch * 8) * 2,                               \
             W + (size_t)(n0 + row) * Cdim + _kb + ch * 8);                      \
    }                                                                            \
} while (0)

    GO_PREFETCH(0);
    CP_COMMIT();

    const int NT = Cdim / 64;   // 12
    for (int kt = 0; kt < NT; kt++) {
        if (kt + 1 < NT) { GO_PREFETCH(kt + 1); CP_COMMIT(); CP_WAIT(1); }
        else             { CP_WAIT(0); }
        __syncthreads();

        uint32_t sA = sbase + (kt & 1) * GO_STG;
        uint32_t sW = sA + GO_MAT;
#pragma unroll
        for (int kk = 0; kk < 64; kk += 16) {
            uint32_t a[4][4], bb[2][4];
#pragma unroll
            for (int mt = 0; mt < 4; mt++)
                LDSM4(a[mt][0], a[mt][1], a[mt][2], a[mt][3],
                      sA + ((wm + mt * 16 + gi + gk * 8) * GO_STRIDE + kk + gh * 8) * 2);
#pragma unroll
            for (int bt = 0; bt < 2; bt++)
                LDSM4(bb[bt][0], bb[bt][1], bb[bt][2], bb[bt][3],
                      sW + ((wn + bt * 16 + gi + gk * 8) * GO_STRIDE + kk + gh * 8) * 2);
#pragma unroll
            for (int mt = 0; mt < 4; mt++)
#pragma unroll
                for (int nt = 0; nt < 4; nt++) {
                    int bt = nt >> 1, od = nt & 1;
                    mma16(acc[mt][nt], a[mt][0], a[mt][1], a[mt][2], a[mt][3],
                          bb[bt][od ? 1 : 0], bb[bt][od ? 3 : 2]);
                }
        }
        __syncthreads();
    }

#pragma unroll
    for (int mt = 0; mt < 4; mt++) {
        int mA = m0 + wm + mt * 16 + r;
        int mB = mA + 8;
#pragma unroll
        for (int nt = 0; nt < 4; nt++) {
            int n = n0 + wn + nt * 8 + 2 * c;
            float2 bv = *(const float2*)&bias[n];
            *(float2*)&Y[(size_t)mA * Cdim + n] =
                make_float2(acc[mt][nt][0] + bv.x, acc[mt][nt][1] + bv.y);
            *(float2*)&Y[(size_t)mB * Cdim + n] =
                make_float2(acc[mt][nt][2] + bv.x, acc[mt][nt][3] + bv.y);
        }
    }
}

// ---------------------------------------------------------------------------
// fp16 flash attention: 128 q/CTA; 128-key superblocks double-buffered;
// ONE softmax pass per 128 keys (s[16][4] spans the superblock);
// skip O-rescale when running max unchanged (warp-uniform).
// ---------------------------------------------------------------------------
#define AT_STRIDE 72
#define AT_SB     (128 * AT_STRIDE * 2)    // 18432 bytes per 128-row block
#define AT_SMEM   (5 * AT_SB)              // Q + 2K + 2V = 92160
#define ONES_H2   0x3C003C00u

__global__ __launch_bounds__(256, 2) void attn_h(
    const __half* __restrict__ Q, const __half* __restrict__ K,
    const __half* __restrict__ V, __half* __restrict__ O)
{
    extern __shared__ __half hs[];
    uint32_t sQ  = smem_u32(hs);
    uint32_t sK0 = sQ + AT_SB;
    uint32_t sV0 = sK0 + 2 * AT_SB;

    int t = threadIdx.x, wid = t >> 5, lane = t & 31;
    int r = lane >> 2, c = lane & 3;
    int gi = lane & 7, gk = (lane >> 3) & 1, gh = lane >> 4;
    int bh = blockIdx.y;
    int b = bh / Hn, h = bh - b * Hn;
    int q0 = blockIdx.x * 128;
    int wm = wid * 16;

    const __half* Qb = Q + ((size_t)bh * Nseq + q0) * Dh;
    const __half* Kb = K + (size_t)bh * Nseq * Dh;
    const __half* Vb = V + (size_t)bh * Nseq * Dh;

    // Stage Q (joins first commit group)
#pragma unroll
    for (int j = 0; j < 4; j++) {
        int idx = t * 4 + j;
        int row = idx >> 3, ch = idx & 7;
        CP16(sQ + (row * AT_STRIDE + ch * 8) * 2, Qb + (size_t)row * Dh + ch * 8);
    }

#define AT_PREFETCH(sb, kt0) do {                                                \
    uint32_t _k = sK0 + (sb) * AT_SB;                                            \
    uint32_t _v = sV0 + (sb) * AT_SB;                                            \
    _Pragma("unroll")                                                            \
    for (int j = 0; j < 4; j++) {                                                \
        int idx = t * 4 + j;                                                     \
        int row = idx >> 3, ch = idx & 7;                                        \
        CP16(_k + (row * AT_STRIDE + ch * 8) * 2,                                \
             Kb + (size_t)((kt0) + row) * Dh + ch * 8);                          \
    }                                                                            \
    _Pragma("unroll")                                                            \
    for (int j = 0; j < 4; j++) {                                                \
        int idx = t * 4 + j;                                                     \
        int row = idx >> 3, ch = idx & 7;                                        \
        CP16(_v + (row * AT_STRIDE + ch * 8) * 2,                                \
             Vb + (size_t)((kt0) + row) * Dh + ch * 8);                          \
    }                                                                            \
} while (0)

    AT_PREFETCH(0, 0);
    CP_COMMIT();

    float m_[2] = { -1e30f, -1e30f };
    float lsum[4] = { 0.0f, 0.0f, 0.0f, 0.0f };
    float o[8][4];
#pragma unroll
    for (int nt = 0; nt < 8; nt++)
#pragma unroll
        for (int i = 0; i < 4; i++) o[nt][i] = 0.0f;

    const int NSB = Nseq / 128;   // 16 superblocks
    for (int it = 0; it < NSB; it++) {
        CP_WAIT(0);
        __syncthreads();

        if (it + 1 < NSB) {
            AT_PREFETCH((it + 1) & 1, (it + 1) * 128);
            CP_COMMIT();
        }

        uint32_t sK = sK0 + (it & 1) * AT_SB;
        uint32_t sV = sV0 + (it & 1) * AT_SB;

        // ---- S = Q K^T over 128 keys (s[16][4]) ----
        float s[16][4];
#pragma unroll
        for (int nt = 0; nt < 16; nt++)
#pragma unroll
            for (int i = 0; i < 4; i++) s[nt][i] = 0.0f;

#pragma unroll
        for (int ks = 0; ks < 4; ks++) {   // d dimension
            int d0 = ks * 16;
            uint32_t a0, a1, a2, a3;
            LDSM4(a0, a1, a2, a3,
                  sQ + ((wm + gi + gk * 8) * AT_STRIDE + d0 + gh * 8) * 2);
#pragma unroll
            for (int kn = 0; kn < 8; kn++) {   // 16-key groups
                uint32_t b0, b1, b2, b3;
                LDSM4(b0, b1, b2, b3,
                      sK + ((kn * 16 + gi + gk * 8) * AT_STRIDE + d0 + gh * 8) * 2);
                mma16(s[kn * 2    ], a0, a1, a2, a3, b0, b2);
                mma16(s[kn * 2 + 1], a0, a1, a2, a3, b1, b3);
            }
        }

        // ---- single softmax pass over 128 keys ----
        float mx0 = -1e30f, mx1 = -1e30f;
#pragma unroll
        for (int nt = 0; nt < 16; nt++) {
            mx0 = fmaxf(mx0, fmaxf(s[nt][0], s[nt][1]));
            mx1 = fmaxf(mx1, fmaxf(s[nt][2], s[nt][3]));
        }
        mx0 = fmaxf(mx0, __shfl_xor_sync(0xffffffffu, mx0, 1));
        mx0 = fmaxf(mx0, __shfl_xor_sync(0xffffffffu, mx0, 2));
        mx1 = fmaxf(mx1, __shfl_xor_sync(0xffffffffu, mx1, 1));
        mx1 = fmaxf(mx1, __shfl_xor_sync(0xffffffffu, mx1, 2));

        float mn0 = fmaxf(m_[0], mx0);
        float mn1 = fmaxf(m_[1], mx1);
        float cor0 = ex2f(m_[0] - mn0);
        float cor1 = ex2f(m_[1] - mn1);
        m_[0] = mn0; m_[1] = mn1;

        // ---- P = exp2(S - m) fp16x2 (packed A-fragments) ----
        uint32_t pp[16][2];
#pragma unroll
        for (int nt = 0; nt < 16; nt++) {
            pp[nt][0] = ex2h2(packh2(s[nt][0] - mn0, s[nt][1] - mn0));
            pp[nt][1] = ex2h2(packh2(s[nt][2] - mn1, s[nt][3] - mn1));
        }

        // ---- rescale O and lsum (skip when max unchanged, warp-uniform) ----
        if (!__all_sync(0xffffffffu, (cor0 == 1.0f) && (cor1 == 1.0f))) {
#pragma unroll
            for (int nt = 0; nt < 8; nt++) {
                o[nt][0] *= cor0; o[nt][1] *= cor0;
                o[nt][2] *= cor1; o[nt][3] *= cor1;
            }
            lsum[0] *= cor0; lsum[1] *= cor0;
            lsum[2] *= cor1; lsum[3] *= cor1;
        }

        // ---- lsum += P @ ones ; O += P V (128 keys) ----
#pragma unroll
        for (int ks = 0; ks < 8; ks++) {
            uint32_t pa0 = pp[2 * ks][0];
            uint32_t pa1 = pp[2 * ks][1];
            uint32_t pa2 = pp[2 * ks + 1][0];
            uint32_t pa3 = pp[2 * ks + 1][1];
            mma16(lsum, pa0, pa1, pa2, pa3, ONES_H2, ONES_H2);
#pragma unroll
            for (int dn = 0; dn < 4; dn++) {
                uint32_t b0, b1, b2, b3;
                LDSM4T(b0, b1, b2, b3,
                       sV + ((ks * 16 + gi + gk * 8) * AT_STRIDE + dn * 16 + gh * 8) * 2);
                mma16(o[dn * 2    ], pa0, pa1, pa2, pa3, b0, b1);
                mma16(o[dn * 2 + 1], pa0, pa1, pa2, pa3, b2, b3);
            }
        }
    }

    float inv0 = 1.0f / lsum[0];
    float inv1 = 1.0f / lsum[2];
    int qg0 = q0 + wm + r;
    int qg1 = qg0 + 8;
#pragma unroll
    for (int nt = 0; nt < 8; nt++) {
        int d = h * Dh + nt * 8 + 2 * c;
        *(uint32_t*)&O[(size_t)(b * Nseq + qg0) * Cdim + d] =
            packh2(o[nt][0] * inv0, o[nt][1] * inv0);
        *(uint32_t*)&O[(size_t)(b * Nseq + qg1) * Cdim + d] =
            packh2(o[nt][2] * inv1, o[nt][3] * inv1);
    }
}

// ---------------------------------------------------------------------------
extern "C" void kernel_launch(void* const* d_in, const int* in_sizes, int n_in,
                              void* d_out, int out_size)
{
    const float* x_q = (const float*)d_in[0];
    const float* x_k = (const float*)d_in[1];
    const float* x_v = (const float*)d_in[2];
    const float* x_u = (const float*)d_in[3];
    const float* Wq  = (const float*)d_in[4];
    const float* Wk  = (const float*)d_in[5];
    const float* Wv  = (const float*)d_in[6];
    const float* Wp  = (const float*)d_in[7];
    const float* bp  = (const float*)d_in[8];
    float* out = (float*)d_out;

    __half *hwq, *hwk, *hwv, *hwp, *hq, *hk, *hv, *ho;
    float *guc;
    cudaGetSymbolAddress((void**)&hwq, g_wq);
    cudaGetSymbolAddress((void**)&hwk, g_wk);
    cudaGetSymbolAddress((void**)&hwv, g_wv);
    cudaGetSymbolAddress((void**)&hwp, g_wp);
    cudaGetSymbolAddress((void**)&hq,  g_q);
    cudaGetSymbolAddress((void**)&hk,  g_k);
    cudaGetSymbolAddress((void**)&hv,  g_v);
    cudaGetSymbolAddress((void**)&ho,  g_o);
    cudaGetSymbolAddress((void**)&guc, g_uc);

    cudaFuncSetAttribute(attn_h,   cudaFuncAttributeMaxDynamicSharedMemorySize, AT_SMEM);
    cudaFuncSetAttribute(gemm_qkv, cudaFuncAttributeMaxDynamicSharedMemorySize, GQ_SMEM);
    cudaFuncSetAttribute(gemm_out, cudaFuncAttributeMaxDynamicSharedMemorySize, GO_SMEM);

    const int NW = Cdim * Cdim;   // 589824
    dim3 f2h_grid(NW / 2048, 4);
    f2h4<<<f2h_grid, 256>>>(Wq, Wk, Wv, Wp, hwq, hwk, hwv, hwp);

    uc_kernel<<<Mrows / 8, 256>>>(x_u, guc);

    dim3 qkv_grid(Cdim / 128, Mrows / 128, 3);   // (6, 64, 3)
    gemm_qkv<<<qkv_grid, 256, GQ_SMEM>>>(x_q, x_k, x_v, hwq, hwk, hwv,
                                         guc, hq, hk, hv);

    dim3 attn_grid(Nseq / 128, Bsz * Hn);        // (16, 48)
    attn_h<<<attn_grid, 256, AT_SMEM>>>(hq, hk, hv, ho);

    dim3 out_grid(Cdim / 128, Mrows / 128);      // (6, 64)
    gemm_out<<<out_grid, 256, GO_SMEM>>>(ho, hwp, bp, out);
}

// round 14
// speedup vs baseline: 1.0573x; 1.0469x over previous
#include <cuda_runtime.h>
#include <cuda_fp16.h>
#include <cstdint>

#define Bsz  4
#define Nseq 2048
#define Cdim 768
#define Hn   12
#define Dh   64
#define Mrows (Bsz * Nseq)   // 8192
#define SCALE_F 0.125f
#define LOG2E_F 1.4426950408889634f

// Scratch
__device__ __half g_wq[Cdim * Cdim];
__device__ __half g_wk[Cdim * Cdim];
__device__ __half g_wv[Cdim * Cdim];
__device__ __half g_wp[Cdim * Cdim];
__device__ __half g_q[Mrows * Cdim];   // [B,H,N,D], uc*SCALE*log2e folded
__device__ __half g_k[Mrows * Cdim];   // [B,H,N,D]
__device__ __half g_v[Mrows * Cdim];   // [B,H,N,D]
__device__ __half g_o[Mrows * Cdim];   // [B,N,C]
__device__ float  g_uc[Mrows];

// ---------------------------------------------------------------------------
__device__ __forceinline__ float ex2f(float x) {
    float y;
    asm("ex2.approx.f32 %0, %1;" : "=f"(y) : "f"(x));
    return y;
}
__device__ __forceinline__ uint32_t ex2h2(uint32_t x) {
    uint32_t y;
    asm("ex2.approx.f16x2 %0, %1;" : "=r"(y) : "r"(x));
    return y;
}
__device__ __forceinline__ uint32_t smem_u32(const void* p) {
    uint32_t a;
    asm("{ .reg .u64 t; cvta.to.shared.u64 t, %1; cvt.u32.u64 %0, t; }" : "=r"(a) : "l"(p));
    return a;
}
__device__ __forceinline__ uint32_t packh2(float a, float b) {
    __half2 h = __floats2half2_rn(a, b);
    return *(uint32_t*)&h;
}
#define CP16(dst, src) \
    asm volatile("cp.async.cg.shared.global [%0], [%1], 16;" :: "r"(dst), "l"(src))
#define CP_COMMIT() asm volatile("cp.async.commit_group;" ::: "memory")
#define CP_WAIT(n)  asm volatile("cp.async.wait_group %0;" :: "n"(n) : "memory")

#define LDSM4(r0, r1, r2, r3, addr) \
    asm volatile("ldmatrix.sync.aligned.m8n8.x4.shared.b16 {%0,%1,%2,%3}, [%4];" \
        : "=r"(r0), "=r"(r1), "=r"(r2), "=r"(r3) : "r"(addr))
#define LDSM4T(r0, r1, r2, r3, addr) \
    asm volatile("ldmatrix.sync.aligned.m8n8.x4.trans.shared.b16 {%0,%1,%2,%3}, [%4];" \
        : "=r"(r0), "=r"(r1), "=r"(r2), "=r"(r3) : "r"(addr))

__device__ __forceinline__ void mma16(float* d,
    uint32_t a0, uint32_t a1, uint32_t a2, uint32_t a3,
    uint32_t b0, uint32_t b1)
{
    asm("mma.sync.aligned.m16n8k16.row.col.f32.f16.f16.f32 "
        "{%0,%1,%2,%3},{%4,%5,%6,%7},{%8,%9},{%0,%1,%2,%3};"
        : "+f"(d[0]), "+f"(d[1]), "+f"(d[2]), "+f"(d[3])
        : "r"(a0), "r"(a1), "r"(a2), "r"(a3), "r"(b0), "r"(b1));
}

// ---------------------------------------------------------------------------
// One fused fp32->fp16 pass for the 4 weight matrices
// ---------------------------------------------------------------------------
__global__ void f2h4(const float* __restrict__ w0, const float* __restrict__ w1,
                     const float* __restrict__ w2, const float* __restrict__ w3,
                     __half* __restrict__ y0, __half* __restrict__ y1,
                     __half* __restrict__ y2, __half* __restrict__ y3)
{
    int which = blockIdx.y;
    const float* x = which == 0 ? w0 : which == 1 ? w1 : which == 2 ? w2 : w3;
    __half* y = which == 0 ? y0 : which == 1 ? y1 : which == 2 ? y2 : y3;
    int i = (blockIdx.x * blockDim.x + threadIdx.x) * 8;
    if (i >= Cdim * Cdim) return;
    float4 v0 = *(const float4*)(x + i);
    float4 v1 = *(const float4*)(x + i + 4);
    *(uint4*)(y + i) = make_uint4(packh2(v0.x, v0.y), packh2(v0.z, v0.w),
                                  packh2(v1.x, v1.y), packh2(v1.z, v1.w));
}

// ---------------------------------------------------------------------------
__global__ void uc_kernel(const float* __restrict__ xu, float* __restrict__ uc)
{
    int warp = (blockIdx.x * blockDim.x + threadIdx.x) >> 5;
    int lane = threadIdx.x & 31;
    if (warp >= Mrows) return;
    const float* row = xu + (size_t)warp * Cdim;
    float s = 0.0f;
#pragma unroll
    for (int i = 0; i < Cdim / 32; i++) s += row[lane + i * 32];
#pragma unroll
    for (int m = 16; m; m >>= 1) s += __shfl_xor_sync(0xffffffffu, s, m);
    if (lane == 0) uc[warp] = s * (1.0f / Cdim);
}

// ---------------------------------------------------------------------------
// Fused QKV projection GEMM, z-batched (unchanged, passing)
// ---------------------------------------------------------------------------
#define GQ_STRIDE  40
#define GQ_A_BYTES (128 * GQ_STRIDE * 2)   // 10240
#define GQ_SMEM    (3 * GQ_A_BYTES)        // 30720

__global__ __launch_bounds__(256, 2) void gemm_qkv(
    const float* __restrict__ xq, const float* __restrict__ xk,
    const float* __restrict__ xv,
    const __half* __restrict__ wq, const __half* __restrict__ wk,
    const __half* __restrict__ wv,
    const float* __restrict__ uc,
    __half* __restrict__ yq, __half* __restrict__ yk, __half* __restrict__ yv)
{
    extern __shared__ __half hs[];
    int z = blockIdx.z;
    const float*  A = z == 0 ? xq : z == 1 ? xk : xv;
    const __half* W = z == 0 ? wq : z == 1 ? wk : wv;
    __half*       Y = z == 0 ? yq : z == 1 ? yk : yv;

    int t = threadIdx.x, wid = t >> 5, lane = t & 31;
    int r = lane >> 2, c = lane & 3;
    int gi = lane & 7, gk = (lane >> 3) & 1, gh = lane >> 4;
    int wm = (wid >> 2) * 64, wn = (wid & 3) * 32;
    int m0 = blockIdx.y * 128, n0 = blockIdx.x * 128;
    uint32_t sA  = smem_u32(hs);
    uint32_t sW0 = sA + GQ_A_BYTES;

    float acc[4][4][4];
#pragma unroll
    for (int mt = 0; mt < 4; mt++)
#pragma unroll
        for (int nt = 0; nt < 4; nt++)
#pragma unroll
            for (int i = 0; i < 4; i++) acc[mt][nt][i] = 0.0f;

    int arow = t >> 1, acg = (t & 1) * 16;
    const float* Ap = A + (size_t)(m0 + arow) * Cdim + acg;
    float4 a4[4];

#define QKV_LOADA(kt) do { int _kb = (kt) * 32;                                  \
    a4[0] = *(const float4*)(Ap + _kb);      a4[1] = *(const float4*)(Ap + _kb + 4);  \
    a4[2] = *(const float4*)(Ap + _kb + 8);  a4[3] = *(const float4*)(Ap + _kb + 12); \
} while (0)

#define QKV_STSA() do {                                                          \
    uint4 u0 = make_uint4(packh2(a4[0].x, a4[0].y), packh2(a4[0].z, a4[0].w),    \
                          packh2(a4[1].x, a4[1].y), packh2(a4[1].z, a4[1].w));   \
    uint4 u1 = make_uint4(packh2(a4[2].x, a4[2].y), packh2(a4[2].z, a4[2].w),    \
                          packh2(a4[3].x, a4[3].y), packh2(a4[3].z, a4[3].w));   \
    *(uint4*)((char*)hs + (arow * GQ_STRIDE + acg) * 2) = u0;                    \
    *(uint4*)((char*)hs + (arow * GQ_STRIDE + acg + 8) * 2) = u1;                \
} while (0)

#define QKV_CPW(kt) do { int _kb = (kt) * 32;                                    \
    uint32_t _bw = sW0 + ((kt) & 1) * GQ_A_BYTES;                                \
    _Pragma("unroll")                                                            \
    for (int j = 0; j < 2; j++) {                                                \
        int idx = t * 2 + j;                                                     \
        int row = idx >> 2, ch = idx & 3;                                        \
        CP16(_bw + (row * GQ_STRIDE + ch * 8) * 2,                               \
             W + (size_t)(n0 + row) * Cdim + _kb + ch * 8);                      \
    }                                                                            \
} while (0)

    QKV_LOADA(0);
    QKV_CPW(0); CP_COMMIT();
    QKV_STSA();
    __syncthreads();

    const int NT = Cdim / 32;   // 24
    for (int kt = 0; kt < NT; kt++) {
        if (kt + 1 < NT) { QKV_LOADA(kt + 1); QKV_CPW(kt + 1); CP_COMMIT(); }
        if (kt < NT - 1) { CP_WAIT(1); } else { CP_WAIT(0); }
        __syncthreads();

        uint32_t bW = sW0 + (kt & 1) * GQ_A_BYTES;
#pragma unroll
        for (int kk = 0; kk < 32; kk += 16) {
            uint32_t a[4][4], bb[2][4];
#pragma unroll
            for (int mt = 0; mt < 4; mt++)
                LDSM4(a[mt][0], a[mt][1], a[mt][2], a[mt][3],
                      sA + ((wm + mt * 16 + gi + gk * 8) * GQ_STRIDE + kk + gh * 8) * 2);
#pragma unroll
            for (int bt = 0; bt < 2; bt++)
                LDSM4(bb[bt][0], bb[bt][1], bb[bt][2], bb[bt][3],
                      bW + ((wn + bt * 16 + gi + gk * 8) * GQ_STRIDE + kk + gh * 8) * 2);
#pragma unroll
            for (int mt = 0; mt < 4; mt++)
#pragma unroll
                for (int nt = 0; nt < 4; nt++) {
                    int bt = nt >> 1, od = nt & 1;
                    mma16(acc[mt][nt], a[mt][0], a[mt][1], a[mt][2], a[mt][3],
                          bb[bt][od ? 1 : 0], bb[bt][od ? 3 : 2]);
                }
        }
        __syncthreads();
        if (kt + 1 < NT) QKV_STSA();
    }

#pragma unroll
    for (int mt = 0; mt < 4; mt++) {
        int mA = m0 + wm + mt * 16 + r;
        int mB = mA + 8;
        float sAs = 1.0f, sBs = 1.0f;
        if (z == 0) {
            sAs = uc[mA] * (SCALE_F * LOG2E_F);
            sBs = uc[mB] * (SCALE_F * LOG2E_F);
        }
        int bA = mA >> 11, nA = mA & (Nseq - 1);
        int bB = mB >> 11, nB = mB & (Nseq - 1);
#pragma unroll
        for (int nt = 0; nt < 4; nt++) {
            int n = n0 + wn + nt * 8 + 2 * c;
            int h = n >> 6, d = n & 63;
            *(uint32_t*)&Y[(((size_t)(bA * Hn + h) * Nseq + nA) << 6) + d] =
                packh2(acc[mt][nt][0] * sAs, acc[mt][nt][1] * sAs);
            *(uint32_t*)&Y[(((size_t)(bB * Hn + h) * Nseq + nB) << 6) + d] =
                packh2(acc[mt][nt][2] * sBs, acc[mt][nt][3] * sBs);
        }
    }
}

// ---------------------------------------------------------------------------
// Output GEMM (round-10 measured-best config): 128x128, BK=64, occ 2.
// ---------------------------------------------------------------------------
#define GO_STRIDE 72
#define GO_MAT    (128 * GO_STRIDE * 2)    // 18432
#define GO_STG    (2 * GO_MAT)             // 36864
#define GO_SMEM   (2 * GO_STG)             // 73728

__global__ __launch_bounds__(256, 2) void gemm_out(
    const __half* __restrict__ A, const __half* __restrict__ W,
    const float* __restrict__ bias, float* __restrict__ Y)
{
    extern __shared__ __half hs[];
    int t = threadIdx.x, wid = t >> 5, lane = t & 31;
    int r = lane >> 2, c = lane & 3;
    int gi = lane & 7, gk = (lane >> 3) & 1, gh = lane >> 4;
    int wm = (wid >> 2) * 64, wn = (wid & 3) * 32;
    int m0 = blockIdx.y * 128, n0 = blockIdx.x * 128;
    uint32_t sbase = smem_u32(hs);

    float acc[4][4][4];
#pragma unroll
    for (int mt = 0; mt < 4; mt++)
#pragma unroll
        for (int nt = 0; nt < 4; nt++)
#pragma unroll
            for (int i = 0; i < 4; i++) acc[mt][nt][i] = 0.0f;

#define GO_PREFETCH(kt) do {                                                     \
    uint32_t _dA = sbase + ((kt) & 1) * GO_STG;                                  \
    uint32_t _dW = _dA + GO_MAT;                                                 \
    int _kb = (kt) * 64;                                                         \
    _Pragma("unroll")                                                            \
    for (int j = 0; j < 4; j++) {                                                \
        int idx = t * 4 + j;                                                     \
        int row = idx >> 3, ch = idx & 7;                                        \
        CP16(_dA + (row * GO_STRIDE + ch * 8) * 2,                               \
             A + (size_t)(m0 + row) * Cdim + _kb + ch * 8);                      \
        CP16(_dW + (row * GO_STRIDE + ch * 8) * 2,                               \
             W + (size_t)(n0 + row) * Cdim + _kb + ch * 8);                      \
    }                                                                            \
} while (0)

    GO_PREFETCH(0);
    CP_COMMIT();

    const int NT = Cdim / 64;   // 12
    for (int kt = 0; kt < NT; kt++) {
        if (kt + 1 < NT) { GO_PREFETCH(kt + 1); CP_COMMIT(); CP_WAIT(1); }
        else             { CP_WAIT(0); }
        __syncthreads();

        uint32_t sA = sbase + (kt & 1) * GO_STG;
        uint32_t sW = sA + GO_MAT;
#pragma unroll
        for (int kk = 0; kk < 64; kk += 16) {
            uint32_t a[4][4], bb[2][4];
#pragma unroll
            for (int mt = 0; mt < 4; mt++)
                LDSM4(a[mt][0], a[mt][1], a[mt][2], a[mt][3],
                      sA + ((wm + mt * 16 + gi + gk * 8) * GO_STRIDE + kk + gh * 8) * 2);
#pragma unroll
            for (int bt = 0; bt < 2; bt++)
                LDSM4(bb[bt][0], bb[bt][1], bb[bt][2], bb[bt][3],
                      sW + ((wn + bt * 16 + gi + gk * 8) * GO_STRIDE + kk + gh * 8) * 2);
#pragma unroll
            for (int mt = 0; mt < 4; mt++)
#pragma unroll
                for (int nt = 0; nt < 4; nt++) {
                    int bt = nt >> 1, od = nt & 1;
                    mma16(acc[mt][nt], a[mt][0], a[mt][1], a[mt][2], a[mt][3],
                          bb[bt][od ? 1 : 0], bb[bt][od ? 3 : 2]);
                }
        }
        __syncthreads();
    }

#pragma unroll
    for (int mt = 0; mt < 4; mt++) {
        int mA = m0 + wm + mt * 16 + r;
        int mB = mA + 8;
#pragma unroll
        for (int nt = 0; nt < 4; nt++) {
            int n = n0 + wn + nt * 8 + 2 * c;
            float2 bv = *(const float2*)&bias[n];
            *(float2*)&Y[(size_t)mA * Cdim + n] =
                make_float2(acc[mt][nt][0] + bv.x, acc[mt][nt][1] + bv.y);
            *(float2*)&Y[(size_t)mB * Cdim + n] =
                make_float2(acc[mt][nt][2] + bv.x, acc[mt][nt][3] + bv.y);
        }
    }
}

// ---------------------------------------------------------------------------
// fp16 flash attention, OCCUPANCY 3: 128 q/CTA; 64-key chunks double-buffered
// (smem 55.3 KB), R10 softmax body (fp16x2 exp, mma-lsum), 85-reg target.
// ---------------------------------------------------------------------------
#define AT_STRIDE 72
#define AT_QB     (128 * AT_STRIDE * 2)    // 18432 bytes (Q)
#define AT_CH     (64 * AT_STRIDE * 2)     // 9216 bytes per 64-key K or V chunk
#define AT_SMEM   (AT_QB + 4 * AT_CH)      // 55296
#define ONES_H2   0x3C003C00u

__global__ __launch_bounds__(256, 3) void attn_h(
    const __half* __restrict__ Q, const __half* __restrict__ K,
    const __half* __restrict__ V, __half* __restrict__ O)
{
    extern __shared__ __half hs[];
    uint32_t sQ  = smem_u32(hs);
    uint32_t sK0 = sQ + AT_QB;               // 2 K chunks
    uint32_t sV0 = sK0 + 2 * AT_CH;          // 2 V chunks

    int t = threadIdx.x, wid = t >> 5, lane = t & 31;
    int r = lane >> 2, c = lane & 3;
    int gi = lane & 7, gk = (lane >> 3) & 1, gh = lane >> 4;
    int bh = blockIdx.y;
    int b = bh / Hn, h = bh - b * Hn;
    int q0 = blockIdx.x * 128;
    int wm = wid * 16;

    const __half* Qb = Q + ((size_t)bh * Nseq + q0) * Dh;
    const __half* Kb = K + (size_t)bh * Nseq * Dh;
    const __half* Vb = V + (size_t)bh * Nseq * Dh;

    // Stage Q (joins first commit group)
#pragma unroll
    for (int j = 0; j < 4; j++) {
        int idx = t * 4 + j;
        int row = idx >> 3, ch = idx & 7;
        CP16(sQ + (row * AT_STRIDE + ch * 8) * 2, Qb + (size_t)row * Dh + ch * 8);
    }

#define AT_PREFETCH(sb, kt0) do {                                                \
    uint32_t _k = sK0 + (sb) * AT_CH;                                            \
    uint32_t _v = sV0 + (sb) * AT_CH;                                            \
    _Pragma("unroll")                                                            \
    for (int j = 0; j < 2; j++) {                                                \
        int idx = t * 2 + j;                                                     \
        int row = idx >> 3, ch = idx & 7;                                        \
        CP16(_k + (row * AT_STRIDE + ch * 8) * 2,                                \
             Kb + (size_t)((kt0) + row) * Dh + ch * 8);                          \
        CP16(_v + (row * AT_STRIDE + ch * 8) * 2,                                \
             Vb + (size_t)((kt0) + row) * Dh + ch * 8);                          \
    }                                                                            \
} while (0)

    AT_PREFETCH(0, 0);
    CP_COMMIT();

    float m_[2] = { -1e30f, -1e30f };
    float lsum[4] = { 0.0f, 0.0f, 0.0f, 0.0f };
    float o[8][4];
#pragma unroll
    for (int nt = 0; nt < 8; nt++)
#pragma unroll
        for (int i = 0; i < 4; i++) o[nt][i] = 0.0f;

    const int NKT = Nseq / 64;   // 32 chunks
    for (int it = 0; it < NKT; it++) {
        CP_WAIT(0);
        __syncthreads();   // chunk(it) ready; all warps past compute(it-1)

        if (it + 1 < NKT) {
            AT_PREFETCH((it + 1) & 1, (it + 1) * 64);
            CP_COMMIT();
        }

        uint32_t sK = sK0 + (it & 1) * AT_CH;
        uint32_t sV = sV0 + (it & 1) * AT_CH;

        // ---- S = Q K^T ----
        float s[8][4];
#pragma unroll
        for (int nt = 0; nt < 8; nt++)
#pragma unroll
            for (int i = 0; i < 4; i++) s[nt][i] = 0.0f;

#pragma unroll
        for (int ks = 0; ks < 4; ks++) {
            int d0 = ks * 16;
            uint32_t a0, a1, a2, a3;
            LDSM4(a0, a1, a2, a3,
                  sQ + ((wm + gi + gk * 8) * AT_STRIDE + d0 + gh * 8) * 2);
#pragma unroll
            for (int kn = 0; kn < 4; kn++) {
                uint32_t b0, b1, b2, b3;
                LDSM4(b0, b1, b2, b3,
                      sK + ((kn * 16 + gi + gk * 8) * AT_STRIDE + d0 + gh * 8) * 2);
                mma16(s[kn * 2    ], a0, a1, a2, a3, b0, b2);
                mma16(s[kn * 2 + 1], a0, a1, a2, a3, b1, b3);
            }
        }

        // ---- row max (fp32) ----
        float mx0 = -1e30f, mx1 = -1e30f;
#pragma unroll
        for (int nt = 0; nt < 8; nt++) {
            mx0 = fmaxf(mx0, fmaxf(s[nt][0], s[nt][1]));
            mx1 = fmaxf(mx1, fmaxf(s[nt][2], s[nt][3]));
        }
        mx0 = fmaxf(mx0, __shfl_xor_sync(0xffffffffu, mx0, 1));
        mx0 = fmaxf(mx0, __shfl_xor_sync(0xffffffffu, mx0, 2));
        mx1 = fmaxf(mx1, __shfl_xor_sync(0xffffffffu, mx1, 1));
        mx1 = fmaxf(mx1, __shfl_xor_sync(0xffffffffu, mx1, 2));

        float mn0 = fmaxf(m_[0], mx0);
        float mn1 = fmaxf(m_[1], mx1);
        float cor0 = ex2f(m_[0] - mn0);
        float cor1 = ex2f(m_[1] - mn1);
        m_[0] = mn0; m_[1] = mn1;

        // ---- P = exp2(S - m) fp16x2 (packed A-frags, overwrites s) ----
        uint32_t pp[8][2];
#pragma unroll
        for (int nt = 0; nt < 8; nt++) {
            pp[nt][0] = ex2h2(packh2(s[nt][0] - mn0, s[nt][1] - mn0));
            pp[nt][1] = ex2h2(packh2(s[nt][2] - mn1, s[nt][3] - mn1));
        }

        // ---- rescale O/lsum (skip when max unchanged, warp-uniform) ----
        if (!__all_sync(0xffffffffu, (cor0 == 1.0f) && (cor1 == 1.0f))) {
#pragma unroll
            for (int nt = 0; nt < 8; nt++) {
                o[nt][0] *= cor0; o[nt][1] *= cor0;
                o[nt][2] *= cor1; o[nt][3] *= cor1;
            }
            lsum[0] *= cor0; lsum[1] *= cor0;
            lsum[2] *= cor1; lsum[3] *= cor1;
        }

        // ---- lsum += P @ ones ; O += P V ----
#pragma unroll
        for (int ks = 0; ks < 4; ks++) {
            uint32_t pa0 = pp[2 * ks][0];
            uint32_t pa1 = pp[2 * ks][1];
            uint32_t pa2 = pp[2 * ks + 1][0];
            uint32_t pa3 = pp[2 * ks + 1][1];
            mma16(lsum, pa0, pa1, pa2, pa3, ONES_H2, ONES_H2);
#pragma unroll
            for (int dn = 0; dn < 4; dn++) {
                uint32_t b0, b1, b2, b3;
                LDSM4T(b0, b1, b2, b3,
                       sV + ((ks * 16 + gi + gk * 8) * AT_STRIDE + dn * 16 + gh * 8) * 2);
                mma16(o[dn * 2    ], pa0, pa1, pa2, pa3, b0, b1);
                mma16(o[dn * 2 + 1], pa0, pa1, pa2, pa3, b2, b3);
            }
        }
    }

    float inv0 = 1.0f / lsum[0];
    float inv1 = 1.0f / lsum[2];
    int qg0 = q0 + wm + r;
    int qg1 = qg0 + 8;
#pragma unroll
    for (int nt = 0; nt < 8; nt++) {
        int d = h * Dh + nt * 8 + 2 * c;
        *(uint32_t*)&O[(size_t)(b * Nseq + qg0) * Cdim + d] =
            packh2(o[nt][0] * inv0, o[nt][1] * inv0);
        *(uint32_t*)&O[(size_t)(b * Nseq + qg1) * Cdim + d] =
            packh2(o[nt][2] * inv1, o[nt][3] * inv1);
    }
}

// ---------------------------------------------------------------------------
extern "C" void kernel_launch(void* const* d_in, const int* in_sizes, int n_in,
                              void* d_out, int out_size)
{
    const float* x_q = (const float*)d_in[0];
    const float* x_k = (const float*)d_in[1];
    const float* x_v = (const float*)d_in[2];
    const float* x_u = (const float*)d_in[3];
    const float* Wq  = (const float*)d_in[4];
    const float* Wk  = (const float*)d_in[5];
    const float* Wv  = (const float*)d_in[6];
    const float* Wp  = (const float*)d_in[7];
    const float* bp  = (const float*)d_in[8];
    float* out = (float*)d_out;

    __half *hwq, *hwk, *hwv, *hwp, *hq, *hk, *hv, *ho;
    float *guc;
    cudaGetSymbolAddress((void**)&hwq, g_wq);
    cudaGetSymbolAddress((void**)&hwk, g_wk);
    cudaGetSymbolAddress((void**)&hwv, g_wv);
    cudaGetSymbolAddress((void**)&hwp, g_wp);
    cudaGetSymbolAddress((void**)&hq,  g_q);
    cudaGetSymbolAddress((void**)&hk,  g_k);
    cudaGetSymbolAddress((void**)&hv,  g_v);
    cudaGetSymbolAddress((void**)&ho,  g_o);
    cudaGetSymbolAddress((void**)&guc, g_uc);

    cudaFuncSetAttribute(attn_h,   cudaFuncAttributeMaxDynamicSharedMemorySize, AT_SMEM);
    cudaFuncSetAttribute(gemm_qkv, cudaFuncAttributeMaxDynamicSharedMemorySize, GQ_SMEM);
    cudaFuncSetAttribute(gemm_out, cudaFuncAttributeMaxDynamicSharedMemorySize, GO_SMEM);

    const int NW = Cdim * Cdim;   // 589824
    dim3 f2h_grid(NW / 2048, 4);
    f2h4<<<f2h_grid, 256>>>(Wq, Wk, Wv, Wp, hwq, hwk, hwv, hwp);

    uc_kernel<<<Mrows / 8, 256>>>(x_u, guc);

    dim3 qkv_grid(Cdim / 128, Mrows / 128, 3);   // (6, 64, 3)
    gemm_qkv<<<qkv_grid, 256, GQ_SMEM>>>(x_q, x_k, x_v, hwq, hwk, hwv,
                                         guc, hq, hk, hv);

    dim3 attn_grid(Nseq / 128, Bsz * Hn);        // (16, 48)
    attn_h<<<attn_grid, 256, AT_SMEM>>>(hq, hk, hv, ho);

    dim3 out_grid(Cdim / 128, Mrows / 128);      // (6, 64)
    gemm_out<<<out_grid, 256, GO_SMEM>>>(ho, hwp, bp, out);
}

// round 15
// speedup vs baseline: 1.0952x; 1.0359x over previous
#include <cuda_runtime.h>
#include <cuda_fp16.h>
#include <cstdint>

#define Bsz  4
#define Nseq 2048
#define Cdim 768
#define Hn   12
#define Dh   64
#define Mrows (Bsz * Nseq)   // 8192
#define SCALE_F 0.125f
#define LOG2E_F 1.4426950408889634f

// Scratch
__device__ __half g_wq[Cdim * Cdim];
__device__ __half g_wk[Cdim * Cdim];
__device__ __half g_wv[Cdim * Cdim];
__device__ __half g_wp[Cdim * Cdim];
__device__ __half g_q[Mrows * Cdim];   // [B,H,N,D], uc*SCALE*log2e folded
__device__ __half g_k[Mrows * Cdim];   // [B,H,N,D]
__device__ __half g_v[Mrows * Cdim];   // [B,H,N,D]
__device__ __half g_o[Mrows * Cdim];   // [B,N,C]
__device__ float  g_uc[Mrows];

// ---------------------------------------------------------------------------
__device__ __forceinline__ float ex2f(float x) {
    float y;
    asm("ex2.approx.f32 %0, %1;" : "=f"(y) : "f"(x));
    return y;
}
__device__ __forceinline__ uint32_t ex2h2(uint32_t x) {
    uint32_t y;
    asm("ex2.approx.f16x2 %0, %1;" : "=r"(y) : "r"(x));
    return y;
}
__device__ __forceinline__ uint32_t smem_u32(const void* p) {
    uint32_t a;
    asm("{ .reg .u64 t; cvta.to.shared.u64 t, %1; cvt.u32.u64 %0, t; }" : "=r"(a) : "l"(p));
    return a;
}
__device__ __forceinline__ uint32_t packh2(float a, float b) {
    __half2 h = __floats2half2_rn(a, b);
    return *(uint32_t*)&h;
}
#define CP16(dst, src) \
    asm volatile("cp.async.cg.shared.global [%0], [%1], 16;" :: "r"(dst), "l"(src))
#define CP_COMMIT() asm volatile("cp.async.commit_group;" ::: "memory")
#define CP_WAIT(n)  asm volatile("cp.async.wait_group %0;" :: "n"(n) : "memory")

#define LDSM4(r0, r1, r2, r3, addr) \
    asm volatile("ldmatrix.sync.aligned.m8n8.x4.shared.b16 {%0,%1,%2,%3}, [%4];" \
        : "=r"(r0), "=r"(r1), "=r"(r2), "=r"(r3) : "r"(addr))
#define LDSM4T(r0, r1, r2, r3, addr) \
    asm volatile("ldmatrix.sync.aligned.m8n8.x4.trans.shared.b16 {%0,%1,%2,%3}, [%4];" \
        : "=r"(r0), "=r"(r1), "=r"(r2), "=r"(r3) : "r"(addr))

__device__ __forceinline__ void mma16(float* d,
    uint32_t a0, uint32_t a1, uint32_t a2, uint32_t a3,
    uint32_t b0, uint32_t b1)
{
    asm("mma.sync.aligned.m16n8k16.row.col.f32.f16.f16.f32 "
        "{%0,%1,%2,%3},{%4,%5,%6,%7},{%8,%9},{%0,%1,%2,%3};"
        : "+f"(d[0]), "+f"(d[1]), "+f"(d[2]), "+f"(d[3])
        : "r"(a0), "r"(a1), "r"(a2), "r"(a3), "r"(b0), "r"(b1));
}

// ---------------------------------------------------------------------------
// Fused prep: y = 0..3 -> fp32->fp16 weight convert; y = 4 -> uc row means
// ---------------------------------------------------------------------------
__global__ void prep_kernel(
    const float* __restrict__ w0, const float* __restrict__ w1,
    const float* __restrict__ w2, const float* __restrict__ w3,
    __half* __restrict__ y0, __half* __restrict__ y1,
    __half* __restrict__ y2, __half* __restrict__ y3,
    const float* __restrict__ xu, float* __restrict__ uc)
{
    int which = blockIdx.y;
    if (which < 4) {
        const float* x = which == 0 ? w0 : which == 1 ? w1 : which == 2 ? w2 : w3;
        __half* y = which == 0 ? y0 : which == 1 ? y1 : which == 2 ? y2 : y3;
        int i = (blockIdx.x * blockDim.x + threadIdx.x) * 8;
        if (i >= Cdim * Cdim) return;
        float4 v0 = *(const float4*)(x + i);
        float4 v1 = *(const float4*)(x + i + 4);
        *(uint4*)(y + i) = make_uint4(packh2(v0.x, v0.y), packh2(v0.z, v0.w),
                                      packh2(v1.x, v1.y), packh2(v1.z, v1.w));
    } else {
        // uc: warp per row; grid.x covers Mrows/8 blocks of 8 warps
        int warp = (blockIdx.x * blockDim.x + threadIdx.x) >> 5;
        int lane = threadIdx.x & 31;
        if (warp >= Mrows) return;
        const float* row = xu + (size_t)warp * Cdim;
        float s = 0.0f;
#pragma unroll
        for (int i = 0; i < Cdim / 32; i++) s += row[lane + i * 32];
#pragma unroll
        for (int m = 16; m; m >>= 1) s += __shfl_xor_sync(0xffffffffu, s, m);
        if (lane == 0) uc[warp] = s * (1.0f / Cdim);
    }
}

// ---------------------------------------------------------------------------
// Fused QKV projection GEMM, z-batched. A DOUBLE-BUFFERED in smem:
// ONE __syncthreads per k-tile (STSA(kt+1) overlaps into the idle buffer).
// ---------------------------------------------------------------------------
#define GQ_STRIDE  40
#define GQ_A_BYTES (128 * GQ_STRIDE * 2)   // 10240
#define GQ_SMEM    (4 * GQ_A_BYTES)        // 2 A bufs + 2 W bufs = 40960

__global__ __launch_bounds__(256, 2) void gemm_qkv(
    const float* __restrict__ xq, const float* __restrict__ xk,
    const float* __restrict__ xv,
    const __half* __restrict__ wq, const __half* __restrict__ wk,
    const __half* __restrict__ wv,
    const float* __restrict__ uc,
    __half* __restrict__ yq, __half* __restrict__ yk, __half* __restrict__ yv)
{
    extern __shared__ __half hs[];
    int z = blockIdx.z;
    const float*  A = z == 0 ? xq : z == 1 ? xk : xv;
    const __half* W = z == 0 ? wq : z == 1 ? wk : wv;
    __half*       Y = z == 0 ? yq : z == 1 ? yk : yv;

    int t = threadIdx.x, wid = t >> 5, lane = t & 31;
    int r = lane >> 2, c = lane & 3;
    int gi = lane & 7, gk = (lane >> 3) & 1, gh = lane >> 4;
    int wm = (wid >> 2) * 64, wn = (wid & 3) * 32;
    int m0 = blockIdx.y * 128, n0 = blockIdx.x * 128;
    uint32_t sA0 = smem_u32(hs);
    uint32_t sW0 = sA0 + 2 * GQ_A_BYTES;

    float acc[4][4][4];
#pragma unroll
    for (int mt = 0; mt < 4; mt++)
#pragma unroll
        for (int nt = 0; nt < 4; nt++)
#pragma unroll
            for (int i = 0; i < 4; i++) acc[mt][nt][i] = 0.0f;

    int arow = t >> 1, acg = (t & 1) * 16;
    const float* Ap = A + (size_t)(m0 + arow) * Cdim + acg;
    float4 a4[4];

#define QKV_LOADA(kt) do { int _kb = (kt) * 32;                                  \
    a4[0] = *(const float4*)(Ap + _kb);      a4[1] = *(const float4*)(Ap + _kb + 4);  \
    a4[2] = *(const float4*)(Ap + _kb + 8);  a4[3] = *(const float4*)(Ap + _kb + 12); \
} while (0)

#define QKV_STSA(buf) do {                                                       \
    char* _dst = (char*)hs + (buf) * GQ_A_BYTES;                                 \
    uint4 u0 = make_uint4(packh2(a4[0].x, a4[0].y), packh2(a4[0].z, a4[0].w),    \
                          packh2(a4[1].x, a4[1].y), packh2(a4[1].z, a4[1].w));   \
    uint4 u1 = make_uint4(packh2(a4[2].x, a4[2].y), packh2(a4[2].z, a4[2].w),    \
                          packh2(a4[3].x, a4[3].y), packh2(a4[3].z, a4[3].w));   \
    *(uint4*)(_dst + (arow * GQ_STRIDE + acg) * 2) = u0;                         \
    *(uint4*)(_dst + (arow * GQ_STRIDE + acg + 8) * 2) = u1;                     \
} while (0)

#define QKV_CPW(kt) do { int _kb = (kt) * 32;                                    \
    uint32_t _bw = sW0 + ((kt) & 1) * GQ_A_BYTES;                                \
    _Pragma("unroll")                                                            \
    for (int j = 0; j < 2; j++) {                                                \
        int idx = t * 2 + j;                                                     \
        int row = idx >> 2, ch = idx & 3;                                        \
        CP16(_bw + (row * GQ_STRIDE + ch * 8) * 2,                               \
             W + (size_t)(n0 + row) * Cdim + _kb + ch * 8);                      \
    }                                                                            \
} while (0)

    // Prologue: stage A(0) and W(0)
    QKV_LOADA(0);
    QKV_CPW(0); CP_COMMIT();
    QKV_STSA(0);

    const int NT = Cdim / 32;   // 24
    for (int kt = 0; kt < NT; kt++) {
        if (kt + 1 < NT) {
            QKV_LOADA(kt + 1);       // global A loads for next tile (registers)
            QKV_CPW(kt + 1); CP_COMMIT();
            CP_WAIT(1);              // W(kt) landed
        } else {
            CP_WAIT(0);
        }
        __syncthreads();             // A(kt) STS visible; prior compute done

        uint32_t bA = sA0 + (kt & 1) * GQ_A_BYTES;
        uint32_t bW = sW0 + (kt & 1) * GQ_A_BYTES;
#pragma unroll
        for (int kk = 0; kk < 32; kk += 16) {
            uint32_t a[4][4], bb[2][4];
#pragma unroll
            for (int mt = 0; mt < 4; mt++)
                LDSM4(a[mt][0], a[mt][1], a[mt][2], a[mt][3],
                      bA + ((wm + mt * 16 + gi + gk * 8) * GQ_STRIDE + kk + gh * 8) * 2);
#pragma unroll
            for (int bt = 0; bt < 2; bt++)
                LDSM4(bb[bt][0], bb[bt][1], bb[bt][2], bb[bt][3],
                      bW + ((wn + bt * 16 + gi + gk * 8) * GQ_STRIDE + kk + gh * 8) * 2);
#pragma unroll
            for (int mt = 0; mt < 4; mt++)
#pragma unroll
                for (int nt = 0; nt < 4; nt++) {
                    int bt = nt >> 1, od = nt & 1;
                    mma16(acc[mt][nt], a[mt][0], a[mt][1], a[mt][2], a[mt][3],
                          bb[bt][od ? 1 : 0], bb[bt][od ? 3 : 2]);
                }
        }
        // Store A(kt+1) into the OTHER buffer — no barrier needed (next
        // iteration's syncthreads publishes it before compute(kt+1)).
        if (kt + 1 < NT) QKV_STSA((kt + 1) & 1);
    }

#pragma unroll
    for (int mt = 0; mt < 4; mt++) {
        int mA = m0 + wm + mt * 16 + r;
        int mB = mA + 8;
        float sAs = 1.0f, sBs = 1.0f;
        if (z == 0) {
            sAs = uc[mA] * (SCALE_F * LOG2E_F);
            sBs = uc[mB] * (SCALE_F * LOG2E_F);
        }
        int bA = mA >> 11, nA = mA & (Nseq - 1);
        int bB = mB >> 11, nB = mB & (Nseq - 1);
#pragma unroll
        for (int nt = 0; nt < 4; nt++) {
            int n = n0 + wn + nt * 8 + 2 * c;
            int h = n >> 6, d = n & 63;
            *(uint32_t*)&Y[(((size_t)(bA * Hn + h) * Nseq + nA) << 6) + d] =
                packh2(acc[mt][nt][0] * sAs, acc[mt][nt][1] * sAs);
            *(uint32_t*)&Y[(((size_t)(bB * Hn + h) * Nseq + nB) << 6) + d] =
                packh2(acc[mt][nt][2] * sBs, acc[mt][nt][3] * sBs);
        }
    }
}

// ---------------------------------------------------------------------------
// Output GEMM (measured-best config): 128x128, BK=64, occ 2.
// ---------------------------------------------------------------------------
#define GO_STRIDE 72
#define GO_MAT    (128 * GO_STRIDE * 2)    // 18432
#define GO_STG    (2 * GO_MAT)             // 36864
#define GO_SMEM   (2 * GO_STG)             // 73728

__global__ __launch_bounds__(256, 2) void gemm_out(
    const __half* __restrict__ A, const __half* __restrict__ W,
    const float* __restrict__ bias, float* __restrict__ Y)
{
    extern __shared__ __half hs[];
    int t = threadIdx.x, wid = t >> 5, lane = t & 31;
    int r = lane >> 2, c = lane & 3;
    int gi = lane & 7, gk = (lane >> 3) & 1, gh = lane >> 4;
    int wm = (wid >> 2) * 64, wn = (wid & 3) * 32;
    int m0 = blockIdx.y * 128, n0 = blockIdx.x * 128;
    uint32_t sbase = smem_u32(hs);

    float acc[4][4][4];
#pragma unroll
    for (int mt = 0; mt < 4; mt++)
#pragma unroll
        for (int nt = 0; nt < 4; nt++)
#pragma unroll
            for (int i = 0; i < 4; i++) acc[mt][nt][i] = 0.0f;

#define GO_PREFETCH(kt) do {                                                     \
    uint32_t _dA = sbase + ((kt) & 1) * GO_STG;                                  \
    uint32_t _dW = _dA + GO_MAT;                                                 \
    int _kb = (kt) * 64;                                                         \
    _Pragma("unroll")                                                            \
    for (int j = 0; j < 4; j++) {                                                \
        int idx = t * 4 + j;                                                     \
        int row = idx >> 3, ch = idx & 7;                                        \
        CP16(_dA + (row * GO_STRIDE + ch * 8) * 2,                               \
             A + (size_t)(m0 + row) * Cdim + _kb + ch * 8);                      \
        CP16(_dW + (row * GO_STRIDE + ch * 8) * 2,                               \
             W + (size_t)(n0 + row) * Cdim + _kb + ch * 8);                      \
    }                                                                            \
} while (0)

    GO_PREFETCH(0);
    CP_COMMIT();

    const int NT = Cdim / 64;   // 12
    for (int kt = 0; kt < NT; kt++) {
        if (kt + 1 < NT) { GO_PREFETCH(kt + 1); CP_COMMIT(); CP_WAIT(1); }
        else             { CP_WAIT(0); }
        __syncthreads();

        uint32_t sA = sbase + (kt & 1) * GO_STG;
        uint32_t sW = sA + GO_MAT;
#pragma unroll
        for (int kk = 0; kk < 64; kk += 16) {
            uint32_t a[4][4], bb[2][4];
#pragma unroll
            for (int mt = 0; mt < 4; mt++)
                LDSM4(a[mt][0], a[mt][1], a[mt][2], a[mt][3],
                      sA + ((wm + mt * 16 + gi + gk * 8) * GO_STRIDE + kk + gh * 8) * 2);
#pragma unroll
            for (int bt = 0; bt < 2; bt++)
                LDSM4(bb[bt][0], bb[bt][1], bb[bt][2], bb[bt][3],
                      sW + ((wn + bt * 16 + gi + gk * 8) * GO_STRIDE + kk + gh * 8) * 2);
#pragma unroll
            for (int mt = 0; mt < 4; mt++)
#pragma unroll
                for (int nt = 0; nt < 4; nt++) {
                    int bt = nt >> 1, od = nt & 1;
                    mma16(acc[mt][nt], a[mt][0], a[mt][1], a[mt][2], a[mt][3],
                          bb[bt][od ? 1 : 0], bb[bt][od ? 3 : 2]);
                }
        }
        __syncthreads();
    }

#pragma unroll
    for (int mt = 0; mt < 4; mt++) {
        int mA = m0 + wm + mt * 16 + r;
        int mB = mA + 8;
#pragma unroll
        for (int nt = 0; nt < 4; nt++) {
            int n = n0 + wn + nt * 8 + 2 * c;
            float2 bv = *(const float2*)&bias[n];
            *(float2*)&Y[(size_t)mA * Cdim + n] =
                make_float2(acc[mt][nt][0] + bv.x, acc[mt][nt][1] + bv.y);
            *(float2*)&Y[(size_t)mB * Cdim + n] =
                make_float2(acc[mt][nt][2] + bv.x, acc[mt][nt][3] + bv.y);
        }
    }
}

// ---------------------------------------------------------------------------
// fp16 flash attention (measured-best, occ 3): 128 q/CTA; 64-key chunks
// double-buffered (55.3 KB smem); fp16x2 exp softmax; mma row-sums.
// ---------------------------------------------------------------------------
#define AT_STRIDE 72
#define AT_QB     (128 * AT_STRIDE * 2)    // 18432 bytes (Q)
#define AT_CH     (64 * AT_STRIDE * 2)     // 9216 bytes per 64-key K or V chunk
#define AT_SMEM   (AT_QB + 4 * AT_CH)      // 55296
#define ONES_H2   0x3C003C00u

__global__ __launch_bounds__(256, 3) void attn_h(
    const __half* __restrict__ Q, const __half* __restrict__ K,
    const __half* __restrict__ V, __half* __restrict__ O)
{
    extern __shared__ __half hs[];
    uint32_t sQ  = smem_u32(hs);
    uint32_t sK0 = sQ + AT_QB;
    uint32_t sV0 = sK0 + 2 * AT_CH;

    int t = threadIdx.x, wid = t >> 5, lane = t & 31;
    int r = lane >> 2, c = lane & 3;
    int gi = lane & 7, gk = (lane >> 3) & 1, gh = lane >> 4;
    int bh = blockIdx.y;
    int b = bh / Hn, h = bh - b * Hn;
    int q0 = blockIdx.x * 128;
    int wm = wid * 16;

    const __half* Qb = Q + ((size_t)bh * Nseq + q0) * Dh;
    const __half* Kb = K + (size_t)bh * Nseq * Dh;
    const __half* Vb = V + (size_t)bh * Nseq * Dh;

#pragma unroll
    for (int j = 0; j < 4; j++) {
        int idx = t * 4 + j;
        int row = idx >> 3, ch = idx & 7;
        CP16(sQ + (row * AT_STRIDE + ch * 8) * 2, Qb + (size_t)row * Dh + ch * 8);
    }

#define AT_PREFETCH(sb, kt0) do {                                                \
    uint32_t _k = sK0 + (sb) * AT_CH;                                            \
    uint32_t _v = sV0 + (sb) * AT_CH;                                            \
    _Pragma("unroll")                                                            \
    for (int j = 0; j < 2; j++) {                                                \
        int idx = t * 2 + j;                                                     \
        int row = idx >> 3, ch = idx & 7;                                        \
        CP16(_k + (row * AT_STRIDE + ch * 8) * 2,                                \
             Kb + (size_t)((kt0) + row) * Dh + ch * 8);                          \
        CP16(_v + (row * AT_STRIDE + ch * 8) * 2,                                \
             Vb + (size_t)((kt0) + row) * Dh + ch * 8);                          \
    }                                                                            \
} while (0)

    AT_PREFETCH(0, 0);
    CP_COMMIT();

    float m_[2] = { -1e30f, -1e30f };
    float lsum[4] = { 0.0f, 0.0f, 0.0f, 0.0f };
    float o[8][4];
#pragma unroll
    for (int nt = 0; nt < 8; nt++)
#pragma unroll
        for (int i = 0; i < 4; i++) o[nt][i] = 0.0f;

    const int NKT = Nseq / 64;   // 32 chunks
    for (int it = 0; it < NKT; it++) {
        CP_WAIT(0);
        __syncthreads();

        if (it + 1 < NKT) {
            AT_PREFETCH((it + 1) & 1, (it + 1) * 64);
            CP_COMMIT();
        }

        uint32_t sK = sK0 + (it & 1) * AT_CH;
        uint32_t sV = sV0 + (it & 1) * AT_CH;

        // ---- S = Q K^T ----
        float s[8][4];
#pragma unroll
        for (int nt = 0; nt < 8; nt++)
#pragma unroll
            for (int i = 0; i < 4; i++) s[nt][i] = 0.0f;

#pragma unroll
        for (int ks = 0; ks < 4; ks++) {
            int d0 = ks * 16;
            uint32_t a0, a1, a2, a3;
            LDSM4(a0, a1, a2, a3,
                  sQ + ((wm + gi + gk * 8) * AT_STRIDE + d0 + gh * 8) * 2);
#pragma unroll
            for (int kn = 0; kn < 4; kn++) {
                uint32_t b0, b1, b2, b3;
                LDSM4(b0, b1, b2, b3,
                      sK + ((kn * 16 + gi + gk * 8) * AT_STRIDE + d0 + gh * 8) * 2);
                mma16(s[kn * 2    ], a0, a1, a2, a3, b0, b2);
                mma16(s[kn * 2 + 1], a0, a1, a2, a3, b1, b3);
            }
        }

        // ---- row max (fp32) ----
        float mx0 = -1e30f, mx1 = -1e30f;
#pragma unroll
        for (int nt = 0; nt < 8; nt++) {
            mx0 = fmaxf(mx0, fmaxf(s[nt][0], s[nt][1]));
            mx1 = fmaxf(mx1, fmaxf(s[nt][2], s[nt][3]));
        }
        mx0 = fmaxf(mx0, __shfl_xor_sync(0xffffffffu, mx0, 1));
        mx0 = fmaxf(mx0, __shfl_xor_sync(0xffffffffu, mx0, 2));
        mx1 = fmaxf(mx1, __shfl_xor_sync(0xffffffffu, mx1, 1));
        mx1 = fmaxf(mx1, __shfl_xor_sync(0xffffffffu, mx1, 2));

        float mn0 = fmaxf(m_[0], mx0);
        float mn1 = fmaxf(m_[1], mx1);
        float cor0 = ex2f(m_[0] - mn0);
        float cor1 = ex2f(m_[1] - mn1);
        m_[0] = mn0; m_[1] = mn1;

        // ---- P = exp2(S - m) fp16x2 ----
        uint32_t pp[8][2];
#pragma unroll
        for (int nt = 0; nt < 8; nt++) {
            pp[nt][0] = ex2h2(packh2(s[nt][0] - mn0, s[nt][1] - mn0));
            pp[nt][1] = ex2h2(packh2(s[nt][2] - mn1, s[nt][3] - mn1));
        }

        // ---- rescale O/lsum (skip when max unchanged, warp-uniform) ----
        if (!__all_sync(0xffffffffu, (cor0 == 1.0f) && (cor1 == 1.0f))) {
#pragma unroll
            for (int nt = 0; nt < 8; nt++) {
                o[nt][0] *= cor0; o[nt][1] *= cor0;
                o[nt][2] *= cor1; o[nt][3] *= cor1;
            }
            lsum[0] *= cor0; lsum[1] *= cor0;
            lsum[2] *= cor1; lsum[3] *= cor1;
        }

        // ---- lsum += P @ ones ; O += P V ----
#pragma unroll
        for (int ks = 0; ks < 4; ks++) {
            uint32_t pa0 = pp[2 * ks][0];
            uint32_t pa1 = pp[2 * ks][1];
            uint32_t pa2 = pp[2 * ks + 1][0];
            uint32_t pa3 = pp[2 * ks + 1][1];
            mma16(lsum, pa0, pa1, pa2, pa3, ONES_H2, ONES_H2);
#pragma unroll
            for (int dn = 0; dn < 4; dn++) {
                uint32_t b0, b1, b2, b3;
                LDSM4T(b0, b1, b2, b3,
                       sV + ((ks * 16 + gi + gk * 8) * AT_STRIDE + dn * 16 + gh * 8) * 2);
                mma16(o[dn * 2    ], pa0, pa1, pa2, pa3, b0, b1);
                mma16(o[dn * 2 + 1], pa0, pa1, pa2, pa3, b2, b3);
            }
        }
    }

    float inv0 = 1.0f / lsum[0];
    float inv1 = 1.0f / lsum[2];
    int qg0 = q0 + wm + r;
    int qg1 = qg0 + 8;
#pragma unroll
    for (int nt = 0; nt < 8; nt++) {
        int d = h * Dh + nt * 8 + 2 * c;
        *(uint32_t*)&O[(size_t)(b * Nseq + qg0) * Cdim + d] =
            packh2(o[nt][0] * inv0, o[nt][1] * inv0);
        *(uint32_t*)&O[(size_t)(b * Nseq + qg1) * Cdim + d] =
            packh2(o[nt][2] * inv1, o[nt][3] * inv1);
    }
}

// ---------------------------------------------------------------------------
extern "C" void kernel_launch(void* const* d_in, const int* in_sizes, int n_in,
                              void* d_out, int out_size)
{
    const float* x_q = (const float*)d_in[0];
    const float* x_k = (const float*)d_in[1];
    const float* x_v = (const float*)d_in[2];
    const float* x_u = (const float*)d_in[3];
    const float* Wq  = (const float*)d_in[4];
    const float* Wk  = (const float*)d_in[5];
    const float* Wv  = (const float*)d_in[6];
    const float* Wp  = (const float*)d_in[7];
    const float* bp  = (const float*)d_in[8];
    float* out = (float*)d_out;

    __half *hwq, *hwk, *hwv, *hwp, *hq, *hk, *hv, *ho;
    float *guc;
    cudaGetSymbolAddress((void**)&hwq, g_wq);
    cudaGetSymbolAddress((void**)&hwk, g_wk);
    cudaGetSymbolAddress((void**)&hwv, g_wv);
    cudaGetSymbolAddress((void**)&hwp, g_wp);
    cudaGetSymbolAddress((void**)&hq,  g_q);
    cudaGetSymbolAddress((void**)&hk,  g_k);
    cudaGetSymbolAddress((void**)&hv,  g_v);
    cudaGetSymbolAddress((void**)&ho,  g_o);
    cudaGetSymbolAddress((void**)&guc, g_uc);

    cudaFuncSetAttribute(attn_h,   cudaFuncAttributeMaxDynamicSharedMemorySize, AT_SMEM);
    cudaFuncSetAttribute(gemm_qkv, cudaFuncAttributeMaxDynamicSharedMemorySize, GQ_SMEM);
    cudaFuncSetAttribute(gemm_out, cudaFuncAttributeMaxDynamicSharedMemorySize, GO_SMEM);

    // Fused prep: weights convert (y=0..3) + uc row means (y=4).
    // grid.x must cover max(NW/2048, Mrows/8) = max(288, 1024) = 1024.
    dim3 prep_grid(1024, 5);
    prep_kernel<<<prep_grid, 256>>>(Wq, Wk, Wv, Wp, hwq, hwk, hwv, hwp,
                                    x_u, guc);

    dim3 qkv_grid(Cdim / 128, Mrows / 128, 3);   // (6, 64, 3)
    gemm_qkv<<<qkv_grid, 256, GQ_SMEM>>>(x_q, x_k, x_v, hwq, hwk, hwv,
                                         guc, hq, hk, hv);

    dim3 attn_grid(Nseq / 128, Bsz * Hn);        // (16, 48)
    attn_h<<<attn_grid, 256, AT_SMEM>>>(hq, hk, hv, ho);

    dim3 out_grid(Cdim / 128, Mrows / 128);      // (6, 64)
    gemm_out<<<out_grid, 256, GO_SMEM>>>(ho, hwp, bp, out);
}